// round 9
// baseline (speedup 1.0000x reference)
#include <cuda_runtime.h>
#include <cstdint>

// Problem constants (fixed shapes per reference)
#define N_NODES 100000
#define F_IN    256
#define H_DIM   128
#define D_DIM   64
#define MAX_E   1700000

// ---------------- scratch (device globals; no allocation allowed) -------------
__device__ __align__(16) int   g_cnt [N_NODES];              // per-dst edge count / fill cursor
__device__ __align__(16) int   g_row [N_NODES + 1];          // CSR row offsets
__device__ __align__(16) float g_dinv[N_NODES];              // rsqrt(deg) incl self-loop
__device__ __align__(16) int2  g_csr [MAX_E];                // {src, norm-as-int-bits}
__device__ __align__(16) float g_h1  [N_NODES * H_DIM];      // x @ W1
__device__ __align__(16) float g_h2  [N_NODES * H_DIM];      // relu(agg1 + b1)
__device__ __align__(16) float g_agg2[N_NODES * H_DIM];      // aggregated h2
__device__ __align__(16) float g_Wc  [H_DIM * 128];          // [Wmu | Wvar] row-major [128,128]
__device__ __align__(16) float g_bc  [128];                  // [bmu | bvar]

// ---------------- CSR build ------------------------------------------------------
__global__ void zero_cnt_kernel() {
    int i = blockIdx.x * blockDim.x + threadIdx.x;
    if (i < N_NODES) g_cnt[i] = 0;
}

__global__ void count_kernel(const int* __restrict__ dst, int E) {
    int i = blockIdx.x * blockDim.x + threadIdx.x;
    if (i < E) atomicAdd(&g_cnt[dst[i]], 1);
}

// Single-block exclusive scan over g_cnt -> g_row, plus dinv, plus cnt reset.
__global__ void scan_kernel() {            // <<<1, 1024>>>
    __shared__ int warp_sums[32];
    __shared__ int s_carry;
    const int tid = threadIdx.x, lane = tid & 31, wid = tid >> 5;
    if (tid == 0) s_carry = 0;
    __syncthreads();
    for (int base = 0; base < N_NODES; base += 1024) {
        int i = base + tid;
        int v = (i < N_NODES) ? g_cnt[i] : 0;
        if (i < N_NODES) {
            g_dinv[i] = rsqrtf((float)v + 1.0f);   // +1 self-loop
            g_cnt[i] = 0;                           // reset as fill cursor
        }
        int x = v;
#pragma unroll
        for (int off = 1; off < 32; off <<= 1) {
            int t = __shfl_up_sync(0xffffffffu, x, off);
            if (lane >= off) x += t;
        }
        if (lane == 31) warp_sums[wid] = x;
        __syncthreads();
        if (wid == 0) {
            int y = warp_sums[lane];
#pragma unroll
            for (int off = 1; off < 32; off <<= 1) {
                int t = __shfl_up_sync(0xffffffffu, y, off);
                if (lane >= off) y += t;
            }
            warp_sums[lane] = y;
        }
        __syncthreads();
        int warp_off = (wid == 0) ? 0 : warp_sums[wid - 1];
        if (i < N_NODES) g_row[i] = s_carry + warp_off + x - v;   // exclusive
        __syncthreads();
        if (tid == 1023) s_carry += warp_sums[31];
        __syncthreads();
    }
    if (threadIdx.x == 0) g_row[N_NODES] = s_carry;
}

__global__ void fill_kernel(const int* __restrict__ src, const int* __restrict__ dst, int E) {
    int e = blockIdx.x * blockDim.x + threadIdx.x;
    if (e >= E) return;
    int s = src[e], d = dst[e];
    int pos = g_row[d] + atomicAdd(&g_cnt[d], 1);
    g_csr[pos] = make_int2(s, __float_as_int(g_dinv[s] * g_dinv[d]));
}

// ---------------- pack [Wmu|Wvar] and [bmu|bvar] -------------------------------
__global__ void pack_w_kernel(const float* __restrict__ Wmu, const float* __restrict__ Wvar,
                              const float* __restrict__ bmu, const float* __restrict__ bvar) {
    int i = blockIdx.x * blockDim.x + threadIdx.x;   // 0 .. 128*128-1
    if (i < H_DIM * 128) {
        int k = i >> 7, c = i & 127;
        g_Wc[i] = (c < D_DIM) ? Wmu[k * D_DIM + c] : Wvar[k * D_DIM + (c - D_DIM)];
    }
    if (i < 128) g_bc[i] = (i < D_DIM) ? bmu[i] : bvar[i - D_DIM];
}

// ---------------- tf32 helpers ---------------------------------------------------
__device__ __forceinline__ uint32_t f2tf32(float f) {
    uint32_t u;
    asm("cvt.rna.tf32.f32 %0, %1;" : "=r"(u) : "f"(f));
    return u;
}

__device__ __forceinline__ void mma_tf32(float* d, const uint32_t* a, const uint32_t* b) {
    asm volatile(
        "mma.sync.aligned.m16n8k8.row.col.f32.tf32.tf32.f32 "
        "{%0,%1,%2,%3}, {%4,%5,%6,%7}, {%8,%9}, {%0,%1,%2,%3};"
        : "+f"(d[0]), "+f"(d[1]), "+f"(d[2]), "+f"(d[3])
        : "r"(a[0]), "r"(a[1]), "r"(a[2]), "r"(a[3]), "r"(b[0]), "r"(b[1]));
}

// ---------------- 3xTF32 tensor-core GEMM: C[M,128] = A[M,K] @ B[K,128] ----------
// Block 128x128, 256 threads = 8 warps as 2(m) x 4(n); warp tile 64x32.
// BK=8 double-buffered. Smem holds tiles in FRAGMENT-MAJOR layout so per-step
// fragment fetch is 12 x LDS.128 (conflict-free) instead of 48 scalar LDS.
//   A frag slot: AF[mtile][lane][reg], lane=(mm&7)*4+(k&3), reg=(mm>>3)+2*(k>>2)
//   B frag slot: BF[ntile][lane][{b0h,b1h,b0l,b1l}], lane=(n&7)*4+(k&3)
// MODE 0: A = x, B = W1 -> g_h1. MODE 1: A = g_agg2, B = g_Wc, +bias -> mu|sigma.
template <int MODE>
__global__ void __launch_bounds__(256)
tgemm_kernel(const float* __restrict__ Ap, const float* __restrict__ Bp,
             float* __restrict__ outMu, float* __restrict__ outSig,
             int M, int K) {
    __shared__ __align__(16) uint32_t AFh[2][8 * 128];    // 8 mtiles x 32 lanes x 4 regs
    __shared__ __align__(16) uint32_t AFl[2][8 * 128];
    __shared__ __align__(16) uint32_t BF [2][16 * 128];   // 16 ntiles x 32 lanes x 4 regs

    const float* A = (MODE == 0) ? Ap : g_agg2;
    const float* B = (MODE == 0) ? Bp : g_Wc;

    const int tid    = threadIdx.x;
    const int lane   = tid & 31;
    const int wid    = tid >> 5;
    const int warp_m = wid >> 2;      // 0..1 (64 rows each)
    const int warp_n = wid & 3;       // 0..3 (32 cols each)
    const int gid    = lane >> 2;     // 0..7
    const int tig    = lane & 3;      // 0..3
    const int row0   = blockIdx.x * 128;

    float acc[4][4][4];
#pragma unroll
    for (int mt = 0; mt < 4; mt++)
#pragma unroll
        for (int nt = 0; nt < 4; nt++)
#pragma unroll
            for (int r = 0; r < 4; r++) acc[mt][nt][r] = 0.0f;

    auto load_tile = [&](int k0, int buf) {
        // ---- A: 128 rows x 8 k. thread: row r = tid>>1, k-quad q = (tid&1)*4
        int r = tid >> 1, q = (tid & 1) * 4;
        int gr = row0 + r;
        float4 va = make_float4(0.f, 0.f, 0.f, 0.f);
        if (gr < M) va = *(const float4*)&A[(size_t)gr * K + k0 + q];
        float av[4] = {va.x, va.y, va.z, va.w};
        int mtile = r >> 4, mm = r & 15;
        int abase = mtile * 128 + (mm >> 3) + 2 * (q >> 2);   // + lane*4
        int lbase = (mm & 7) * 4;                              // + j
#pragma unroll
        for (int j = 0; j < 4; j++) {
            uint32_t hi = f2tf32(av[j]);
            float lo = av[j] - __uint_as_float(hi);
            int slot = abase + (lbase + j) * 4;
            AFh[buf][slot] = hi;
            AFl[buf][slot] = f2tf32(lo);
        }
        // ---- B: 8 k x 128 n. thread: k row bk = tid>>5, n-quad bn = (tid&31)*4
        int bk = tid >> 5, bn = (tid & 31) * 4;
        float4 vb = *(const float4*)&B[(size_t)(k0 + bk) * 128 + bn];
        float bv[4] = {vb.x, vb.y, vb.z, vb.w};
        int btig = bk & 3, half = bk >> 2;
        int ntile = bn >> 3;                                   // 4-aligned quad stays in 1 ntile
        int nb = bn & 7;                                       // 0 or 4
#pragma unroll
        for (int j = 0; j < 4; j++) {
            uint32_t hi = f2tf32(bv[j]);
            float lo = bv[j] - __uint_as_float(hi);
            int slot = ntile * 128 + ((nb + j) * 4 + btig) * 4;
            BF[buf][slot + half]     = hi;
            BF[buf][slot + 2 + half] = f2tf32(lo);
        }
    };

    const int steps = K / 8;
    load_tile(0, 0);
    __syncthreads();

    for (int s = 0; s < steps; s++) {
        if (s + 1 < steps) load_tile((s + 1) * 8, (s + 1) & 1);
        const int cb = s & 1;

        uint4 fah[4], fal[4], fb[4];
#pragma unroll
        for (int mt = 0; mt < 4; mt++) {
            int mtile = warp_m * 4 + mt;
            fah[mt] = *(const uint4*)&AFh[cb][mtile * 128 + lane * 4];
            fal[mt] = *(const uint4*)&AFl[cb][mtile * 128 + lane * 4];
        }
#pragma unroll
        for (int nt = 0; nt < 4; nt++) {
            int ntile = warp_n * 4 + nt;
            fb[nt] = *(const uint4*)&BF[cb][ntile * 128 + lane * 4];
        }
#pragma unroll
        for (int mt = 0; mt < 4; mt++)
#pragma unroll
            for (int nt = 0; nt < 4; nt++) {
                uint32_t bh[2] = {fb[nt].x, fb[nt].y};
                uint32_t bl[2] = {fb[nt].z, fb[nt].w};
                mma_tf32(acc[mt][nt], (const uint32_t*)&fah[mt], bh);
                mma_tf32(acc[mt][nt], (const uint32_t*)&fah[mt], bl);
                mma_tf32(acc[mt][nt], (const uint32_t*)&fal[mt], bh);
            }
        __syncthreads();
    }

    // Epilogue. c0,c1 -> row gid, cols 2tig,2tig+1; c2,c3 -> row gid+8.
#pragma unroll
    for (int mt = 0; mt < 4; mt++) {
#pragma unroll
        for (int nt = 0; nt < 4; nt++) {
            int col = warp_n * 32 + nt * 8 + 2 * tig;
            int ra  = row0 + warp_m * 64 + mt * 16 + gid;
            int rb  = ra + 8;
            if (MODE == 0) {
                if (ra < M) *(float2*)&g_h1[(size_t)ra * 128 + col] =
                    make_float2(acc[mt][nt][0], acc[mt][nt][1]);
                if (rb < M) *(float2*)&g_h1[(size_t)rb * 128 + col] =
                    make_float2(acc[mt][nt][2], acc[mt][nt][3]);
            } else {
                float b0 = g_bc[col], b1 = g_bc[col + 1];
                float* baseA;
                float* baseB;
                if (col < 64) {
                    baseA = outMu + (size_t)ra * D_DIM + col;
                    baseB = outMu + (size_t)rb * D_DIM + col;
                } else {
                    baseA = outSig + (size_t)ra * D_DIM + (col - 64);
                    baseB = outSig + (size_t)rb * D_DIM + (col - 64);
                }
                if (ra < M) *(float2*)baseA =
                    make_float2(acc[mt][nt][0] + b0, acc[mt][nt][1] + b1);
                if (rb < M) *(float2*)baseB =
                    make_float2(acc[mt][nt][2] + b0, acc[mt][nt][3] + b1);
            }
        }
    }
}

// ---------------- CSR gather-aggregate --------------------------------------------
// One warp per node; LAYER 0: reads g_h1, writes g_h2 = relu(agg + b1) (relu fused)
// LAYER 1: reads g_h2, writes g_agg2.
template <int LAYER>
__global__ void __launch_bounds__(256)
aggregate_kernel(const float* __restrict__ b1) {
    int n    = (blockIdx.x * 256 + threadIdx.x) >> 5;
    int lane = threadIdx.x & 31;
    if (n >= N_NODES) return;

    const float* h = (LAYER == 0) ? g_h1 : g_h2;

    float di = g_dinv[n];
    float d2 = di * di;
    float4 acc = ((const float4*)(h + (size_t)n * 128))[lane];
    acc.x *= d2; acc.y *= d2; acc.z *= d2; acc.w *= d2;

    int r0 = g_row[n], r1 = g_row[n + 1];
    for (int base = r0; base < r1; base += 32) {
        int rem = min(r1 - base, 32);
        int2 ent = make_int2(0, 0);
        if (lane < rem) ent = g_csr[base + lane];

        int k = 0;
        for (; k + 4 <= rem; k += 4) {
            int   s0 = __shfl_sync(0xffffffffu, ent.x, k + 0);
            int   s1 = __shfl_sync(0xffffffffu, ent.x, k + 1);
            int   s2 = __shfl_sync(0xffffffffu, ent.x, k + 2);
            int   s3 = __shfl_sync(0xffffffffu, ent.x, k + 3);
            float w0 = __int_as_float(__shfl_sync(0xffffffffu, ent.y, k + 0));
            float w1 = __int_as_float(__shfl_sync(0xffffffffu, ent.y, k + 1));
            float w2 = __int_as_float(__shfl_sync(0xffffffffu, ent.y, k + 2));
            float w3 = __int_as_float(__shfl_sync(0xffffffffu, ent.y, k + 3));
            float4 v0 = ((const float4*)(h + (size_t)s0 * 128))[lane];
            float4 v1 = ((const float4*)(h + (size_t)s1 * 128))[lane];
            float4 v2 = ((const float4*)(h + (size_t)s2 * 128))[lane];
            float4 v3 = ((const float4*)(h + (size_t)s3 * 128))[lane];
            acc.x = fmaf(v0.x, w0, acc.x); acc.y = fmaf(v0.y, w0, acc.y);
            acc.z = fmaf(v0.z, w0, acc.z); acc.w = fmaf(v0.w, w0, acc.w);
            acc.x = fmaf(v1.x, w1, acc.x); acc.y = fmaf(v1.y, w1, acc.y);
            acc.z = fmaf(v1.z, w1, acc.z); acc.w = fmaf(v1.w, w1, acc.w);
            acc.x = fmaf(v2.x, w2, acc.x); acc.y = fmaf(v2.y, w2, acc.y);
            acc.z = fmaf(v2.z, w2, acc.z); acc.w = fmaf(v2.w, w2, acc.w);
            acc.x = fmaf(v3.x, w3, acc.x); acc.y = fmaf(v3.y, w3, acc.y);
            acc.z = fmaf(v3.z, w3, acc.z); acc.w = fmaf(v3.w, w3, acc.w);
        }
        for (; k < rem; k++) {
            int   s = __shfl_sync(0xffffffffu, ent.x, k);
            float w = __int_as_float(__shfl_sync(0xffffffffu, ent.y, k));
            float4 v = ((const float4*)(h + (size_t)s * 128))[lane];
            acc.x = fmaf(v.x, w, acc.x); acc.y = fmaf(v.y, w, acc.y);
            acc.z = fmaf(v.z, w, acc.z); acc.w = fmaf(v.w, w, acc.w);
        }
    }

    if (LAYER == 0) {
        float4 b = ((const float4*)b1)[lane];
        acc.x = fmaxf(acc.x + b.x, 0.0f);
        acc.y = fmaxf(acc.y + b.y, 0.0f);
        acc.z = fmaxf(acc.z + b.z, 0.0f);
        acc.w = fmaxf(acc.w + b.w, 0.0f);
        ((float4*)(g_h2 + (size_t)n * 128))[lane] = acc;
    } else {
        ((float4*)(g_agg2 + (size_t)n * 128))[lane] = acc;
    }
}

// --------------------------------------------------------------------------------
extern "C" void kernel_launch(void* const* d_in, const int* in_sizes, int n_in,
                              void* d_out, int out_size) {
    const float* x    = (const float*)d_in[0];
    const int*   ei   = (const int*)d_in[1];     // edge_index: int32
    const float* W1   = (const float*)d_in[2];
    const float* b1   = (const float*)d_in[3];
    const float* Wmu  = (const float*)d_in[4];
    const float* bmu  = (const float*)d_in[5];
    const float* Wvar = (const float*)d_in[6];
    const float* bvar = (const float*)d_in[7];

    const int E = in_sizes[1] / 2;
    const int* src = ei;
    const int* dst = ei + E;

    float* outMu  = (float*)d_out;
    float* outSig = (float*)d_out + (size_t)N_NODES * D_DIM;

    const int aggBlocks = (N_NODES * 32 + 255) / 256;   // one warp per node

    // 1-3: CSR counts + scan
    zero_cnt_kernel<<<(N_NODES + 255) / 256, 256>>>();
    count_kernel  <<<(E + 255) / 256, 256>>>(dst, E);
    scan_kernel   <<<1, 1024>>>();

    // 4: layer-1 tf32 GEMM (h1) — ncu capture slot
    tgemm_kernel<0><<<(N_NODES + 127) / 128, 256>>>(x, W1, nullptr, nullptr, N_NODES, F_IN);

    // 5: CSR fill (independent of GEMM)
    fill_kernel<<<(E + 255) / 256, 256>>>(src, dst, E);

    // 6: layer-1 aggregate + fused relu (writes h2)
    aggregate_kernel<0><<<aggBlocks, 256>>>(b1);

    // 7: layer-2 aggregate (agg2)
    aggregate_kernel<1><<<aggBlocks, 256>>>(nullptr);

    // 8: pack fused projection weights
    pack_w_kernel<<<(H_DIM * 128 + 255) / 256, 256>>>(Wmu, Wvar, bmu, bvar);

    // 9: fused mu/sigma tf32 GEMM into d_out
    tgemm_kernel<1><<<(N_NODES + 127) / 128, 256>>>(nullptr, nullptr, outMu, outSig,
                                                    N_NODES, H_DIM);
}

// round 10
// speedup vs baseline: 1.5532x; 1.5532x over previous
#include <cuda_runtime.h>
#include <cstdint>

// Problem constants (fixed shapes per reference)
#define N_NODES 100000
#define F_IN    256
#define H_DIM   128
#define D_DIM   64
#define MAX_E   1700000

// ---------------- scratch (device globals; no allocation allowed) -------------
__device__ __align__(16) int   g_cnt [N_NODES];              // per-dst edge count / fill cursor
__device__ __align__(16) int   g_row [N_NODES + 1];          // CSR row offsets
__device__ __align__(16) float g_dinv[N_NODES];              // rsqrt(deg) incl self-loop
__device__ __align__(16) int2  g_csr [MAX_E];                // {src, norm-as-int-bits}
__device__ __align__(16) float g_h1  [N_NODES * H_DIM];      // x @ W1
__device__ __align__(16) float g_h2  [N_NODES * H_DIM];      // relu(agg1 + b1)
__device__ __align__(16) float g_agg2[N_NODES * H_DIM];      // aggregated h2
__device__ __align__(16) float g_bc  [128];                  // [bmu | bvar]
// Precomputed B fragments (fragment-major, hi/lo 3xTF32 split):
//   index = (kstep*16 + ntile)*32 + lane, value = {b0h, b1h, b0l, b1l}
__device__ __align__(16) uint4 g_Bf1[32 * 16 * 32];          // W1:  K=256 -> 32 ksteps
__device__ __align__(16) uint4 g_Bf2[16 * 16 * 32];          // Wc:  K=128 -> 16 ksteps

// ---------------- CSR build ------------------------------------------------------
__global__ void zero_cnt_kernel() {
    int i = blockIdx.x * blockDim.x + threadIdx.x;
    if (i < N_NODES) g_cnt[i] = 0;
}

__global__ void count_kernel(const int* __restrict__ dst, int E) {
    int i = blockIdx.x * blockDim.x + threadIdx.x;
    if (i < E) atomicAdd(&g_cnt[dst[i]], 1);
}

// Single-block exclusive scan over g_cnt -> g_row, plus dinv, plus cnt reset.
__global__ void scan_kernel() {            // <<<1, 1024>>>
    __shared__ int warp_sums[32];
    __shared__ int s_carry;
    const int tid = threadIdx.x, lane = tid & 31, wid = tid >> 5;
    if (tid == 0) s_carry = 0;
    __syncthreads();
    for (int base = 0; base < N_NODES; base += 1024) {
        int i = base + tid;
        int v = (i < N_NODES) ? g_cnt[i] : 0;
        if (i < N_NODES) {
            g_dinv[i] = rsqrtf((float)v + 1.0f);   // +1 self-loop
            g_cnt[i] = 0;                           // reset as fill cursor
        }
        int x = v;
#pragma unroll
        for (int off = 1; off < 32; off <<= 1) {
            int t = __shfl_up_sync(0xffffffffu, x, off);
            if (lane >= off) x += t;
        }
        if (lane == 31) warp_sums[wid] = x;
        __syncthreads();
        if (wid == 0) {
            int y = warp_sums[lane];
#pragma unroll
            for (int off = 1; off < 32; off <<= 1) {
                int t = __shfl_up_sync(0xffffffffu, y, off);
                if (lane >= off) y += t;
            }
            warp_sums[lane] = y;
        }
        __syncthreads();
        int warp_off = (wid == 0) ? 0 : warp_sums[wid - 1];
        if (i < N_NODES) g_row[i] = s_carry + warp_off + x - v;   // exclusive
        __syncthreads();
        if (tid == 1023) s_carry += warp_sums[31];
        __syncthreads();
    }
    if (threadIdx.x == 0) g_row[N_NODES] = s_carry;
}

__global__ void fill_kernel(const int* __restrict__ src, const int* __restrict__ dst, int E) {
    int e = blockIdx.x * blockDim.x + threadIdx.x;
    if (e >= E) return;
    int s = src[e], d = dst[e];
    int pos = g_row[d] + atomicAdd(&g_cnt[d], 1);
    g_csr[pos] = make_int2(s, __float_as_int(g_dinv[s] * g_dinv[d]));
}

// ---------------- tf32 helpers ---------------------------------------------------
__device__ __forceinline__ uint32_t f2tf32(float f) {
    uint32_t u;
    asm("cvt.rna.tf32.f32 %0, %1;" : "=r"(u) : "f"(f));
    return u;
}

__device__ __forceinline__ void mma_tf32(float* d, const uint32_t* a, const uint32_t* b) {
    asm volatile(
        "mma.sync.aligned.m16n8k8.row.col.f32.tf32.tf32.f32 "
        "{%0,%1,%2,%3}, {%4,%5,%6,%7}, {%8,%9}, {%0,%1,%2,%3};"
        : "+f"(d[0]), "+f"(d[1]), "+f"(d[2]), "+f"(d[3])
        : "r"(a[0]), "r"(a[1]), "r"(a[2]), "r"(a[3]), "r"(b[0]), "r"(b[1]));
}

// ---------------- B fragment precompute ------------------------------------------
// Fragment mapping (m16n8k8 B, col layout): thread lane -> gid=lane>>2, tig=lane&3;
// b0 = B[kstep*8 + tig][n0+gid], b1 = B[kstep*8 + tig + 4][n0+gid].
__global__ void pack_bfrag1_kernel(const float* __restrict__ W1) {
    int i = blockIdx.x * blockDim.x + threadIdx.x;   // 0 .. 32*16*32-1
    if (i >= 32 * 16 * 32) return;
    int lane = i & 31, nt = (i >> 5) & 15, s = i >> 9;
    int gid = lane >> 2, tig = lane & 3;
    int n = nt * 8 + gid;
    int k0 = s * 8 + tig, k1 = k0 + 4;
    float b0 = W1[k0 * 128 + n];
    float b1 = W1[k1 * 128 + n];
    uint32_t h0 = f2tf32(b0), h1 = f2tf32(b1);
    uint32_t l0 = f2tf32(b0 - __uint_as_float(h0));
    uint32_t l1 = f2tf32(b1 - __uint_as_float(h1));
    g_Bf1[i] = make_uint4(h0, h1, l0, l1);
}

__global__ void pack_bfrag2_kernel(const float* __restrict__ Wmu, const float* __restrict__ Wvar,
                                   const float* __restrict__ bmu, const float* __restrict__ bvar) {
    int i = blockIdx.x * blockDim.x + threadIdx.x;
    if (i < 128) g_bc[i] = (i < D_DIM) ? bmu[i] : bvar[i - D_DIM];
    if (i >= 16 * 16 * 32) return;
    int lane = i & 31, nt = (i >> 5) & 15, s = i >> 9;
    int gid = lane >> 2, tig = lane & 3;
    int n = nt * 8 + gid;
    int k0 = s * 8 + tig, k1 = k0 + 4;
    float b0 = (n < D_DIM) ? Wmu[k0 * D_DIM + n] : Wvar[k0 * D_DIM + (n - D_DIM)];
    float b1 = (n < D_DIM) ? Wmu[k1 * D_DIM + n] : Wvar[k1 * D_DIM + (n - D_DIM)];
    uint32_t h0 = f2tf32(b0), h1 = f2tf32(b1);
    uint32_t l0 = f2tf32(b0 - __uint_as_float(h0));
    uint32_t l1 = f2tf32(b1 - __uint_as_float(h1));
    g_Bf2[i] = make_uint4(h0, h1, l0, l1);
}

// ---------------- 3xTF32 tensor-core GEMM: C[M,128] = A[M,K] @ B[K,128] ----------
// Block 128x128, 256 threads = 8 warps as 2(m) x 4(n); warp tile 64x32.
// BK=8 double-buffered A in smem ([k][m], as in the 460us R7 kernel).
// B fragments come PRE-SPLIT from global fragment-major buffers (weights are
// block-invariant): 4 x LDG.128 per warp-step, L2/L1-resident.
// MODE 0: A = x -> g_h1. MODE 1: A = g_agg2, +bias -> mu|sigma.
template <int MODE>
__global__ void __launch_bounds__(256, 2)
tgemm_kernel(const float* __restrict__ Ap,
             float* __restrict__ outMu, float* __restrict__ outSig,
             int M, int K) {
    __shared__ __align__(16) uint32_t Ah[2][8][136];
    __shared__ __align__(16) uint32_t Al[2][8][136];

    const float* A  = (MODE == 0) ? Ap : g_agg2;
    const uint4* Bf = (MODE == 0) ? g_Bf1 : g_Bf2;

    const int tid    = threadIdx.x;
    const int lane   = tid & 31;
    const int wid    = tid >> 5;
    const int warp_m = wid >> 2;      // 0..1 (64 rows each)
    const int warp_n = wid & 3;       // 0..3 (32 cols each)
    const int gid    = lane >> 2;     // 0..7
    const int tig    = lane & 3;      // 0..3
    const int row0   = blockIdx.x * 128;

    float acc[4][4][4];
#pragma unroll
    for (int mt = 0; mt < 4; mt++)
#pragma unroll
        for (int nt = 0; nt < 4; nt++)
#pragma unroll
            for (int r = 0; r < 4; r++) acc[mt][nt][r] = 0.0f;

    auto load_tile = [&](int k0, int buf) {
        // A: 128 rows x 8 k. thread: r = tid>>1 (row), qq = (tid&1)*4 (k-quad)
        int r = tid >> 1, qq = (tid & 1) * 4;
        int gr = row0 + r;
        float4 va = make_float4(0.f, 0.f, 0.f, 0.f);
        if (gr < M) va = *(const float4*)&A[(size_t)gr * K + k0 + qq];
        float av[4] = {va.x, va.y, va.z, va.w};
#pragma unroll
        for (int j = 0; j < 4; j++) {
            uint32_t hi = f2tf32(av[j]);
            float lo = av[j] - __uint_as_float(hi);
            Ah[buf][qq + j][r] = hi;
            Al[buf][qq + j][r] = f2tf32(lo);
        }
    };

    const int steps = K / 8;
    load_tile(0, 0);
    __syncthreads();

    const uint4* BfW = Bf + (size_t)warp_n * 4 * 32 + lane;   // + s*16*32 + nt*32

    for (int s = 0; s < steps; s++) {
        // B fragments for this step first (independent LDG.128, L2/L1-hot)
        uint4 fb[4];
#pragma unroll
        for (int nt = 0; nt < 4; nt++)
            fb[nt] = __ldg(&BfW[(size_t)s * 16 * 32 + nt * 32]);

        if (s + 1 < steps) load_tile((s + 1) * 8, (s + 1) & 1);
        const int cb = s & 1;

        uint32_t fah[4][4], fal[4][4];
#pragma unroll
        for (int mt = 0; mt < 4; mt++) {
            int m0 = warp_m * 64 + mt * 16;
            fah[mt][0] = Ah[cb][tig][m0 + gid];
            fah[mt][1] = Ah[cb][tig][m0 + 8 + gid];
            fah[mt][2] = Ah[cb][tig + 4][m0 + gid];
            fah[mt][3] = Ah[cb][tig + 4][m0 + 8 + gid];
            fal[mt][0] = Al[cb][tig][m0 + gid];
            fal[mt][1] = Al[cb][tig][m0 + 8 + gid];
            fal[mt][2] = Al[cb][tig + 4][m0 + gid];
            fal[mt][3] = Al[cb][tig + 4][m0 + 8 + gid];
        }
#pragma unroll
        for (int mt = 0; mt < 4; mt++)
#pragma unroll
            for (int nt = 0; nt < 4; nt++) {
                uint32_t bh[2] = {fb[nt].x, fb[nt].y};
                uint32_t bl[2] = {fb[nt].z, fb[nt].w};
                mma_tf32(acc[mt][nt], fah[mt], bh);
                mma_tf32(acc[mt][nt], fah[mt], bl);
                mma_tf32(acc[mt][nt], fal[mt], bh);
            }
        __syncthreads();
    }

    // Epilogue. c0,c1 -> row gid, cols 2tig,2tig+1; c2,c3 -> row gid+8.
#pragma unroll
    for (int mt = 0; mt < 4; mt++) {
#pragma unroll
        for (int nt = 0; nt < 4; nt++) {
            int col = warp_n * 32 + nt * 8 + 2 * tig;
            int ra  = row0 + warp_m * 64 + mt * 16 + gid;
            int rb  = ra + 8;
            if (MODE == 0) {
                if (ra < M) *(float2*)&g_h1[(size_t)ra * 128 + col] =
                    make_float2(acc[mt][nt][0], acc[mt][nt][1]);
                if (rb < M) *(float2*)&g_h1[(size_t)rb * 128 + col] =
                    make_float2(acc[mt][nt][2], acc[mt][nt][3]);
            } else {
                float b0 = g_bc[col], b1 = g_bc[col + 1];
                float* baseA;
                float* baseB;
                if (col < 64) {
                    baseA = outMu + (size_t)ra * D_DIM + col;
                    baseB = outMu + (size_t)rb * D_DIM + col;
                } else {
                    baseA = outSig + (size_t)ra * D_DIM + (col - 64);
                    baseB = outSig + (size_t)rb * D_DIM + (col - 64);
                }
                if (ra < M) *(float2*)baseA =
                    make_float2(acc[mt][nt][0] + b0, acc[mt][nt][1] + b1);
                if (rb < M) *(float2*)baseB =
                    make_float2(acc[mt][nt][2] + b0, acc[mt][nt][3] + b1);
            }
        }
    }
}

// ---------------- CSR gather-aggregate --------------------------------------------
// One warp per node; LAYER 0: reads g_h1, writes g_h2 = relu(agg + b1) (relu fused)
// LAYER 1: reads g_h2, writes g_agg2.
template <int LAYER>
__global__ void __launch_bounds__(256)
aggregate_kernel(const float* __restrict__ b1) {
    int n    = (blockIdx.x * 256 + threadIdx.x) >> 5;
    int lane = threadIdx.x & 31;
    if (n >= N_NODES) return;

    const float* h = (LAYER == 0) ? g_h1 : g_h2;

    float di = g_dinv[n];
    float d2 = di * di;
    float4 acc = ((const float4*)(h + (size_t)n * 128))[lane];
    acc.x *= d2; acc.y *= d2; acc.z *= d2; acc.w *= d2;

    int r0 = g_row[n], r1 = g_row[n + 1];
    for (int base = r0; base < r1; base += 32) {
        int rem = min(r1 - base, 32);
        int2 ent = make_int2(0, 0);
        if (lane < rem) ent = g_csr[base + lane];

        int k = 0;
        for (; k + 4 <= rem; k += 4) {
            int   s0 = __shfl_sync(0xffffffffu, ent.x, k + 0);
            int   s1 = __shfl_sync(0xffffffffu, ent.x, k + 1);
            int   s2 = __shfl_sync(0xffffffffu, ent.x, k + 2);
            int   s3 = __shfl_sync(0xffffffffu, ent.x, k + 3);
            float w0 = __int_as_float(__shfl_sync(0xffffffffu, ent.y, k + 0));
            float w1 = __int_as_float(__shfl_sync(0xffffffffu, ent.y, k + 1));
            float w2 = __int_as_float(__shfl_sync(0xffffffffu, ent.y, k + 2));
            float w3 = __int_as_float(__shfl_sync(0xffffffffu, ent.y, k + 3));
            float4 v0 = ((const float4*)(h + (size_t)s0 * 128))[lane];
            float4 v1 = ((const float4*)(h + (size_t)s1 * 128))[lane];
            float4 v2 = ((const float4*)(h + (size_t)s2 * 128))[lane];
            float4 v3 = ((const float4*)(h + (size_t)s3 * 128))[lane];
            acc.x = fmaf(v0.x, w0, acc.x); acc.y = fmaf(v0.y, w0, acc.y);
            acc.z = fmaf(v0.z, w0, acc.z); acc.w = fmaf(v0.w, w0, acc.w);
            acc.x = fmaf(v1.x, w1, acc.x); acc.y = fmaf(v1.y, w1, acc.y);
            acc.z = fmaf(v1.z, w1, acc.z); acc.w = fmaf(v1.w, w1, acc.w);
            acc.x = fmaf(v2.x, w2, acc.x); acc.y = fmaf(v2.y, w2, acc.y);
            acc.z = fmaf(v2.z, w2, acc.z); acc.w = fmaf(v2.w, w2, acc.w);
            acc.x = fmaf(v3.x, w3, acc.x); acc.y = fmaf(v3.y, w3, acc.y);
            acc.z = fmaf(v3.z, w3, acc.z); acc.w = fmaf(v3.w, w3, acc.w);
        }
        for (; k < rem; k++) {
            int   s = __shfl_sync(0xffffffffu, ent.x, k);
            float w = __int_as_float(__shfl_sync(0xffffffffu, ent.y, k));
            float4 v = ((const float4*)(h + (size_t)s * 128))[lane];
            acc.x = fmaf(v.x, w, acc.x); acc.y = fmaf(v.y, w, acc.y);
            acc.z = fmaf(v.z, w, acc.z); acc.w = fmaf(v.w, w, acc.w);
        }
    }

    if (LAYER == 0) {
        float4 b = ((const float4*)b1)[lane];
        acc.x = fmaxf(acc.x + b.x, 0.0f);
        acc.y = fmaxf(acc.y + b.y, 0.0f);
        acc.z = fmaxf(acc.z + b.z, 0.0f);
        acc.w = fmaxf(acc.w + b.w, 0.0f);
        ((float4*)(g_h2 + (size_t)n * 128))[lane] = acc;
    } else {
        ((float4*)(g_agg2 + (size_t)n * 128))[lane] = acc;
    }
}

// --------------------------------------------------------------------------------
extern "C" void kernel_launch(void* const* d_in, const int* in_sizes, int n_in,
                              void* d_out, int out_size) {
    const float* x    = (const float*)d_in[0];
    const int*   ei   = (const int*)d_in[1];     // edge_index: int32
    const float* W1   = (const float*)d_in[2];
    const float* b1   = (const float*)d_in[3];
    const float* Wmu  = (const float*)d_in[4];
    const float* bmu  = (const float*)d_in[5];
    const float* Wvar = (const float*)d_in[6];
    const float* bvar = (const float*)d_in[7];

    const int E = in_sizes[1] / 2;
    const int* src = ei;
    const int* dst = ei + E;

    float* outMu  = (float*)d_out;
    float* outSig = (float*)d_out + (size_t)N_NODES * D_DIM;

    const int aggBlocks = (N_NODES * 32 + 255) / 256;   // one warp per node

    // 1-3: CSR counts + W1 fragment pack
    zero_cnt_kernel <<<(N_NODES + 255) / 256, 256>>>();
    count_kernel    <<<(E + 255) / 256, 256>>>(dst, E);
    pack_bfrag1_kernel<<<(32 * 16 * 32 + 255) / 256, 256>>>(W1);

    // 4: layer-1 tf32 GEMM (h1) — ncu capture slot
    tgemm_kernel<0><<<(N_NODES + 127) / 128, 256>>>(x, nullptr, nullptr, N_NODES, F_IN);

    // 5-6: scan + CSR fill (overlap-independent of GEMM output)
    scan_kernel<<<1, 1024>>>();
    fill_kernel<<<(E + 255) / 256, 256>>>(src, dst, E);

    // 7: layer-1 aggregate + fused relu (writes h2)
    aggregate_kernel<0><<<aggBlocks, 256>>>(b1);

    // 8: layer-2 aggregate (agg2)
    aggregate_kernel<1><<<aggBlocks, 256>>>(nullptr);

    // 9: pack projection fragments + bias
    pack_bfrag2_kernel<<<(16 * 16 * 32 + 255) / 256, 256>>>(Wmu, Wvar, bmu, bvar);

    // 10: fused mu/sigma tf32 GEMM into d_out
    tgemm_kernel<1><<<(N_NODES + 127) / 128, 256>>>(nullptr, outMu, outSig, N_NODES, H_DIM);
}

// round 11
// speedup vs baseline: 1.7451x; 1.1236x over previous
#include <cuda_runtime.h>
#include <cuda_fp16.h>
#include <cstdint>

// Problem constants (fixed shapes per reference)
#define N_NODES 100000
#define F_IN    256
#define H_DIM   128
#define D_DIM   64
#define MAX_E   1700000

// ---------------- scratch (device globals; no allocation allowed) -------------
__device__ __align__(16) int    g_cnt [N_NODES];             // per-dst edge count / fill cursor
__device__ __align__(16) int    g_row [N_NODES + 1];         // CSR row offsets
__device__ __align__(16) float  g_dinv[N_NODES];             // rsqrt(deg) incl self-loop
__device__ __align__(16) int2   g_csr [MAX_E];               // {src, norm-as-int-bits}
__device__ __align__(16) __half g_h1  [N_NODES * H_DIM];     // x @ W1        (fp16 storage)
__device__ __align__(16) __half g_h2  [N_NODES * H_DIM];     // relu(agg1+b1) (fp16 storage)
__device__ __align__(16) float  g_agg2[N_NODES * H_DIM];     // aggregated h2 (fp32)
__device__ __align__(16) float  g_bc  [128];                 // [bmu | bvar]
// Precomputed B fragments (fragment-major, hi/lo 3xTF32 split):
//   index = (kstep*16 + ntile)*32 + lane, value = {b0h, b1h, b0l, b1l}
__device__ __align__(16) uint4 g_Bf1[32 * 16 * 32];          // W1:  K=256 -> 32 ksteps
__device__ __align__(16) uint4 g_Bf2[16 * 16 * 32];          // Wc:  K=128 -> 16 ksteps

// ---------------- fp16 pack/unpack helpers ---------------------------------------
__device__ __forceinline__ float4 h4_to_f4(uint2 u) {
    float2 f0 = __half22float2(*(const __half2*)&u.x);
    float2 f1 = __half22float2(*(const __half2*)&u.y);
    return make_float4(f0.x, f0.y, f1.x, f1.y);
}
__device__ __forceinline__ uint2 f4_to_h4(float4 v) {
    __half2 h0 = __floats2half2_rn(v.x, v.y);
    __half2 h1 = __floats2half2_rn(v.z, v.w);
    uint2 u;
    u.x = *(const uint32_t*)&h0;
    u.y = *(const uint32_t*)&h1;
    return u;
}

// ---------------- CSR build ------------------------------------------------------
__global__ void zero_cnt_kernel() {
    int i = blockIdx.x * blockDim.x + threadIdx.x;
    if (i < N_NODES) g_cnt[i] = 0;
}

__global__ void count_kernel(const int* __restrict__ dst, int E) {
    int i = blockIdx.x * blockDim.x + threadIdx.x;
    if (i < E) atomicAdd(&g_cnt[dst[i]], 1);
}

// Single-block exclusive scan over g_cnt -> g_row, plus dinv, plus cnt reset.
__global__ void scan_kernel() {            // <<<1, 1024>>>
    __shared__ int warp_sums[32];
    __shared__ int s_carry;
    const int tid = threadIdx.x, lane = tid & 31, wid = tid >> 5;
    if (tid == 0) s_carry = 0;
    __syncthreads();
    for (int base = 0; base < N_NODES; base += 1024) {
        int i = base + tid;
        int v = (i < N_NODES) ? g_cnt[i] : 0;
        if (i < N_NODES) {
            g_dinv[i] = rsqrtf((float)v + 1.0f);   // +1 self-loop
            g_cnt[i] = 0;                           // reset as fill cursor
        }
        int x = v;
#pragma unroll
        for (int off = 1; off < 32; off <<= 1) {
            int t = __shfl_up_sync(0xffffffffu, x, off);
            if (lane >= off) x += t;
        }
        if (lane == 31) warp_sums[wid] = x;
        __syncthreads();
        if (wid == 0) {
            int y = warp_sums[lane];
#pragma unroll
            for (int off = 1; off < 32; off <<= 1) {
                int t = __shfl_up_sync(0xffffffffu, y, off);
                if (lane >= off) y += t;
            }
            warp_sums[lane] = y;
        }
        __syncthreads();
        int warp_off = (wid == 0) ? 0 : warp_sums[wid - 1];
        if (i < N_NODES) g_row[i] = s_carry + warp_off + x - v;   // exclusive
        __syncthreads();
        if (tid == 1023) s_carry += warp_sums[31];
        __syncthreads();
    }
    if (threadIdx.x == 0) g_row[N_NODES] = s_carry;
}

__global__ void fill_kernel(const int* __restrict__ src, const int* __restrict__ dst, int E) {
    int e = blockIdx.x * blockDim.x + threadIdx.x;
    if (e >= E) return;
    int s = src[e], d = dst[e];
    int pos = g_row[d] + atomicAdd(&g_cnt[d], 1);
    g_csr[pos] = make_int2(s, __float_as_int(g_dinv[s] * g_dinv[d]));
}

// ---------------- tf32 helpers ---------------------------------------------------
__device__ __forceinline__ uint32_t f2tf32(float f) {
    uint32_t u;
    asm("cvt.rna.tf32.f32 %0, %1;" : "=r"(u) : "f"(f));
    return u;
}

__device__ __forceinline__ void mma_tf32(float* d, const uint32_t* a, const uint32_t* b) {
    asm volatile(
        "mma.sync.aligned.m16n8k8.row.col.f32.tf32.tf32.f32 "
        "{%0,%1,%2,%3}, {%4,%5,%6,%7}, {%8,%9}, {%0,%1,%2,%3};"
        : "+f"(d[0]), "+f"(d[1]), "+f"(d[2]), "+f"(d[3])
        : "r"(a[0]), "r"(a[1]), "r"(a[2]), "r"(a[3]), "r"(b[0]), "r"(b[1]));
}

// ---------------- B fragment precompute ------------------------------------------
// Fragment mapping (m16n8k8 B, col layout): lane -> gid=lane>>2, tig=lane&3;
// b0 = B[kstep*8 + tig][n0+gid], b1 = B[kstep*8 + tig + 4][n0+gid].
__global__ void pack_bfrag1_kernel(const float* __restrict__ W1) {
    int i = blockIdx.x * blockDim.x + threadIdx.x;   // 0 .. 32*16*32-1
    if (i >= 32 * 16 * 32) return;
    int lane = i & 31, nt = (i >> 5) & 15, s = i >> 9;
    int gid = lane >> 2, tig = lane & 3;
    int n = nt * 8 + gid;
    int k0 = s * 8 + tig, k1 = k0 + 4;
    float b0 = W1[k0 * 128 + n];
    float b1 = W1[k1 * 128 + n];
    uint32_t h0 = f2tf32(b0), h1 = f2tf32(b1);
    uint32_t l0 = f2tf32(b0 - __uint_as_float(h0));
    uint32_t l1 = f2tf32(b1 - __uint_as_float(h1));
    g_Bf1[i] = make_uint4(h0, h1, l0, l1);
}

__global__ void pack_bfrag2_kernel(const float* __restrict__ Wmu, const float* __restrict__ Wvar,
                                   const float* __restrict__ bmu, const float* __restrict__ bvar) {
    int i = blockIdx.x * blockDim.x + threadIdx.x;
    if (i < 128) g_bc[i] = (i < D_DIM) ? bmu[i] : bvar[i - D_DIM];
    if (i >= 16 * 16 * 32) return;
    int lane = i & 31, nt = (i >> 5) & 15, s = i >> 9;
    int gid = lane >> 2, tig = lane & 3;
    int n = nt * 8 + gid;
    int k0 = s * 8 + tig, k1 = k0 + 4;
    float b0 = (n < D_DIM) ? Wmu[k0 * D_DIM + n] : Wvar[k0 * D_DIM + (n - D_DIM)];
    float b1 = (n < D_DIM) ? Wmu[k1 * D_DIM + n] : Wvar[k1 * D_DIM + (n - D_DIM)];
    uint32_t h0 = f2tf32(b0), h1 = f2tf32(b1);
    uint32_t l0 = f2tf32(b0 - __uint_as_float(h0));
    uint32_t l1 = f2tf32(b1 - __uint_as_float(h1));
    g_Bf2[i] = make_uint4(h0, h1, l0, l1);
}

// ---------------- 3xTF32 tensor-core GEMM: C[M,128] = A[M,K] @ B[K,128] ----------
// Block 128x128, 256 threads = 8 warps as 2(m) x 4(n); warp tile 64x32.
// BK=8 double-buffered A in smem ([k][m]); B fragments pre-split in global
// fragment-major buffers (weights are block-invariant): 4 x LDG.128/warp-step.
// MODE 0: A = x -> g_h1 (fp16). MODE 1: A = g_agg2, +bias -> mu|sigma (fp32).
template <int MODE>
__global__ void __launch_bounds__(256, 2)
tgemm_kernel(const float* __restrict__ Ap,
             float* __restrict__ outMu, float* __restrict__ outSig,
             int M, int K) {
    __shared__ __align__(16) uint32_t Ah[2][8][136];
    __shared__ __align__(16) uint32_t Al[2][8][136];

    const float* A  = (MODE == 0) ? Ap : g_agg2;
    const uint4* Bf = (MODE == 0) ? g_Bf1 : g_Bf2;

    const int tid    = threadIdx.x;
    const int lane   = tid & 31;
    const int wid    = tid >> 5;
    const int warp_m = wid >> 2;      // 0..1 (64 rows each)
    const int warp_n = wid & 3;       // 0..3 (32 cols each)
    const int gid    = lane >> 2;     // 0..7
    const int tig    = lane & 3;      // 0..3
    const int row0   = blockIdx.x * 128;

    float acc[4][4][4];
#pragma unroll
    for (int mt = 0; mt < 4; mt++)
#pragma unroll
        for (int nt = 0; nt < 4; nt++)
#pragma unroll
            for (int r = 0; r < 4; r++) acc[mt][nt][r] = 0.0f;

    auto load_tile = [&](int k0, int buf) {
        int r = tid >> 1, qq = (tid & 1) * 4;
        int gr = row0 + r;
        float4 va = make_float4(0.f, 0.f, 0.f, 0.f);
        if (gr < M) va = *(const float4*)&A[(size_t)gr * K + k0 + qq];
        float av[4] = {va.x, va.y, va.z, va.w};
#pragma unroll
        for (int j = 0; j < 4; j++) {
            uint32_t hi = f2tf32(av[j]);
            float lo = av[j] - __uint_as_float(hi);
            Ah[buf][qq + j][r] = hi;
            Al[buf][qq + j][r] = f2tf32(lo);
        }
    };

    const int steps = K / 8;
    load_tile(0, 0);
    __syncthreads();

    const uint4* BfW = Bf + (size_t)warp_n * 4 * 32 + lane;   // + s*16*32 + nt*32

    for (int s = 0; s < steps; s++) {
        uint4 fb[4];
#pragma unroll
        for (int nt = 0; nt < 4; nt++)
            fb[nt] = __ldg(&BfW[(size_t)s * 16 * 32 + nt * 32]);

        if (s + 1 < steps) load_tile((s + 1) * 8, (s + 1) & 1);
        const int cb = s & 1;

        uint32_t fah[4][4], fal[4][4];
#pragma unroll
        for (int mt = 0; mt < 4; mt++) {
            int m0 = warp_m * 64 + mt * 16;
            fah[mt][0] = Ah[cb][tig][m0 + gid];
            fah[mt][1] = Ah[cb][tig][m0 + 8 + gid];
            fah[mt][2] = Ah[cb][tig + 4][m0 + gid];
            fah[mt][3] = Ah[cb][tig + 4][m0 + 8 + gid];
            fal[mt][0] = Al[cb][tig][m0 + gid];
            fal[mt][1] = Al[cb][tig][m0 + 8 + gid];
            fal[mt][2] = Al[cb][tig + 4][m0 + gid];
            fal[mt][3] = Al[cb][tig + 4][m0 + 8 + gid];
        }
#pragma unroll
        for (int mt = 0; mt < 4; mt++)
#pragma unroll
            for (int nt = 0; nt < 4; nt++) {
                uint32_t bh[2] = {fb[nt].x, fb[nt].y};
                uint32_t bl[2] = {fb[nt].z, fb[nt].w};
                mma_tf32(acc[mt][nt], fah[mt], bh);
                mma_tf32(acc[mt][nt], fah[mt], bl);
                mma_tf32(acc[mt][nt], fal[mt], bh);
            }
        __syncthreads();
    }

    // Epilogue. c0,c1 -> row gid, cols 2tig,2tig+1; c2,c3 -> row gid+8.
#pragma unroll
    for (int mt = 0; mt < 4; mt++) {
#pragma unroll
        for (int nt = 0; nt < 4; nt++) {
            int col = warp_n * 32 + nt * 8 + 2 * tig;
            int ra  = row0 + warp_m * 64 + mt * 16 + gid;
            int rb  = ra + 8;
            if (MODE == 0) {
                if (ra < M) *(__half2*)&g_h1[(size_t)ra * 128 + col] =
                    __floats2half2_rn(acc[mt][nt][0], acc[mt][nt][1]);
                if (rb < M) *(__half2*)&g_h1[(size_t)rb * 128 + col] =
                    __floats2half2_rn(acc[mt][nt][2], acc[mt][nt][3]);
            } else {
                float b0 = g_bc[col], b1 = g_bc[col + 1];
                float* baseA;
                float* baseB;
                if (col < 64) {
                    baseA = outMu + (size_t)ra * D_DIM + col;
                    baseB = outMu + (size_t)rb * D_DIM + col;
                } else {
                    baseA = outSig + (size_t)ra * D_DIM + (col - 64);
                    baseB = outSig + (size_t)rb * D_DIM + (col - 64);
                }
                if (ra < M) *(float2*)baseA =
                    make_float2(acc[mt][nt][0] + b0, acc[mt][nt][1] + b1);
                if (rb < M) *(float2*)baseB =
                    make_float2(acc[mt][nt][2] + b0, acc[mt][nt][3] + b1);
            }
        }
    }
}

// ---------------- CSR gather-aggregate (fp16 h rows, fp32 accumulate) -------------
// One warp per node; each lane covers 4 features (8B fp16 load per row).
// LAYER 0: reads g_h1, writes g_h2 = relu(agg + b1) as fp16 (relu fused)
// LAYER 1: reads g_h2, writes g_agg2 as fp32 (feeds 3xTF32 GEMM2).
template <int LAYER>
__global__ void __launch_bounds__(256)
aggregate_kernel(const float* __restrict__ b1) {
    int n    = (blockIdx.x * 256 + threadIdx.x) >> 5;
    int lane = threadIdx.x & 31;
    if (n >= N_NODES) return;

    const __half* h = (LAYER == 0) ? g_h1 : g_h2;

    float di = g_dinv[n];
    float d2 = di * di;
    float4 acc = h4_to_f4(((const uint2*)(h + (size_t)n * 128))[lane]);
    acc.x *= d2; acc.y *= d2; acc.z *= d2; acc.w *= d2;

    int r0 = g_row[n], r1 = g_row[n + 1];
    for (int base = r0; base < r1; base += 32) {
        int rem = min(r1 - base, 32);
        int2 ent = make_int2(0, 0);
        if (lane < rem) ent = g_csr[base + lane];

        int k = 0;
        for (; k + 4 <= rem; k += 4) {
            int   s0 = __shfl_sync(0xffffffffu, ent.x, k + 0);
            int   s1 = __shfl_sync(0xffffffffu, ent.x, k + 1);
            int   s2 = __shfl_sync(0xffffffffu, ent.x, k + 2);
            int   s3 = __shfl_sync(0xffffffffu, ent.x, k + 3);
            float w0 = __int_as_float(__shfl_sync(0xffffffffu, ent.y, k + 0));
            float w1 = __int_as_float(__shfl_sync(0xffffffffu, ent.y, k + 1));
            float w2 = __int_as_float(__shfl_sync(0xffffffffu, ent.y, k + 2));
            float w3 = __int_as_float(__shfl_sync(0xffffffffu, ent.y, k + 3));
            uint2 u0 = ((const uint2*)(h + (size_t)s0 * 128))[lane];
            uint2 u1 = ((const uint2*)(h + (size_t)s1 * 128))[lane];
            uint2 u2 = ((const uint2*)(h + (size_t)s2 * 128))[lane];
            uint2 u3 = ((const uint2*)(h + (size_t)s3 * 128))[lane];
            float4 v0 = h4_to_f4(u0);
            float4 v1 = h4_to_f4(u1);
            float4 v2 = h4_to_f4(u2);
            float4 v3 = h4_to_f4(u3);
            acc.x = fmaf(v0.x, w0, acc.x); acc.y = fmaf(v0.y, w0, acc.y);
            acc.z = fmaf(v0.z, w0, acc.z); acc.w = fmaf(v0.w, w0, acc.w);
            acc.x = fmaf(v1.x, w1, acc.x); acc.y = fmaf(v1.y, w1, acc.y);
            acc.z = fmaf(v1.z, w1, acc.z); acc.w = fmaf(v1.w, w1, acc.w);
            acc.x = fmaf(v2.x, w2, acc.x); acc.y = fmaf(v2.y, w2, acc.y);
            acc.z = fmaf(v2.z, w2, acc.z); acc.w = fmaf(v2.w, w2, acc.w);
            acc.x = fmaf(v3.x, w3, acc.x); acc.y = fmaf(v3.y, w3, acc.y);
            acc.z = fmaf(v3.z, w3, acc.z); acc.w = fmaf(v3.w, w3, acc.w);
        }
        for (; k < rem; k++) {
            int   s = __shfl_sync(0xffffffffu, ent.x, k);
            float w = __int_as_float(__shfl_sync(0xffffffffu, ent.y, k));
            float4 v = h4_to_f4(((const uint2*)(h + (size_t)s * 128))[lane]);
            acc.x = fmaf(v.x, w, acc.x); acc.y = fmaf(v.y, w, acc.y);
            acc.z = fmaf(v.z, w, acc.z); acc.w = fmaf(v.w, w, acc.w);
        }
    }

    if (LAYER == 0) {
        float4 b = ((const float4*)b1)[lane];
        acc.x = fmaxf(acc.x + b.x, 0.0f);
        acc.y = fmaxf(acc.y + b.y, 0.0f);
        acc.z = fmaxf(acc.z + b.z, 0.0f);
        acc.w = fmaxf(acc.w + b.w, 0.0f);
        ((uint2*)(g_h2 + (size_t)n * 128))[lane] = f4_to_h4(acc);
    } else {
        ((float4*)(g_agg2 + (size_t)n * 128))[lane] = acc;
    }
}

// --------------------------------------------------------------------------------
extern "C" void kernel_launch(void* const* d_in, const int* in_sizes, int n_in,
                              void* d_out, int out_size) {
    const float* x    = (const float*)d_in[0];
    const int*   ei   = (const int*)d_in[1];     // edge_index: int32
    const float* W1   = (const float*)d_in[2];
    const float* b1   = (const float*)d_in[3];
    const float* Wmu  = (const float*)d_in[4];
    const float* bmu  = (const float*)d_in[5];
    const float* Wvar = (const float*)d_in[6];
    const float* bvar = (const float*)d_in[7];

    const int E = in_sizes[1] / 2;
    const int* src = ei;
    const int* dst = ei + E;

    float* outMu  = (float*)d_out;
    float* outSig = (float*)d_out + (size_t)N_NODES * D_DIM;

    const int aggBlocks = (N_NODES * 32 + 255) / 256;   // one warp per node

    // 1-3: CSR counts + W1 fragment pack
    zero_cnt_kernel <<<(N_NODES + 255) / 256, 256>>>();
    count_kernel    <<<(E + 255) / 256, 256>>>(dst, E);
    pack_bfrag1_kernel<<<(32 * 16 * 32 + 255) / 256, 256>>>(W1);

    // 4: layer-1 tf32 GEMM (h1, fp16 out) — ncu capture slot
    tgemm_kernel<0><<<(N_NODES + 127) / 128, 256>>>(x, nullptr, nullptr, N_NODES, F_IN);

    // 5-6: scan + CSR fill
    scan_kernel<<<1, 1024>>>();
    fill_kernel<<<(E + 255) / 256, 256>>>(src, dst, E);

    // 7: layer-1 aggregate + fused relu (writes h2, fp16)
    aggregate_kernel<0><<<aggBlocks, 256>>>(b1);

    // 8: layer-2 aggregate (agg2, fp32)
    aggregate_kernel<1><<<aggBlocks, 256>>>(nullptr);

    // 9: pack projection fragments + bias
    pack_bfrag2_kernel<<<(16 * 16 * 32 + 255) / 256, 256>>>(Wmu, Wvar, bmu, bvar);

    // 10: fused mu/sigma tf32 GEMM into d_out
    tgemm_kernel<1><<<(N_NODES + 127) / 128, 256>>>(nullptr, outMu, outSig, N_NODES, H_DIM);
}

// round 13
// speedup vs baseline: 2.1999x; 1.2606x over previous
#include <cuda_runtime.h>
#include <cuda_fp16.h>
#include <cstdint>

// Problem constants (fixed shapes per reference)
#define N_NODES 100000
#define F_IN    256
#define H_DIM   128
#define D_DIM   64
#define MAX_E   1700000

// ---------------- scratch (device globals; no allocation allowed) -------------
__device__ __align__(16) int    g_cnt [N_NODES];             // per-dst edge count / fill cursor
__device__ __align__(16) int    g_row [N_NODES + 1];         // CSR row offsets
__device__ __align__(16) float  g_dinv[N_NODES];             // rsqrt(deg) incl self-loop
__device__ __align__(16) int2   g_csr [MAX_E];               // {src, norm-as-int-bits}
__device__ __align__(16) __half g_h1  [N_NODES * H_DIM];     // x @ W1        (fp16 storage)
__device__ __align__(16) __half g_h2  [N_NODES * H_DIM];     // relu(agg1+b1) (fp16 storage)
__device__ __align__(16) float  g_agg2[N_NODES * H_DIM];     // aggregated h2 (fp32)
__device__ __align__(16) float  g_bc  [128];                 // [bmu | bvar]
// Precomputed B fragments for m16n8k16 fp16 mma (2-split hi/lo):
//   index = (kstep16*16 + ntile)*32 + lane, value = {bh0, bh1, bl0, bl1} (f16x2 each)
__device__ __align__(16) uint4 g_Bf1[16 * 16 * 32];          // W1:  K=256 -> 16 ksteps
__device__ __align__(16) uint4 g_Bf2[ 8 * 16 * 32];          // Wc:  K=128 ->  8 ksteps

// ---------------- fp16 pack/unpack helpers ---------------------------------------
__device__ __forceinline__ float4 h4_to_f4(uint2 u) {
    float2 f0 = __half22float2(*(const __half2*)&u.x);
    float2 f1 = __half22float2(*(const __half2*)&u.y);
    return make_float4(f0.x, f0.y, f1.x, f1.y);
}
__device__ __forceinline__ uint2 f4_to_h4(float4 v) {
    __half2 h0 = __floats2half2_rn(v.x, v.y);
    __half2 h1 = __floats2half2_rn(v.z, v.w);
    uint2 u;
    u.x = *(const uint32_t*)&h0;
    u.y = *(const uint32_t*)&h1;
    return u;
}
__device__ __forceinline__ uint32_t pack_h2(float x, float y) {
    __half2 h = __floats2half2_rn(x, y);
    return *(const uint32_t*)&h;
}

// ---------------- CSR build ------------------------------------------------------
__global__ void zero_cnt_kernel() {
    int i = blockIdx.x * blockDim.x + threadIdx.x;
    if (i < N_NODES) g_cnt[i] = 0;
}

__global__ void count_kernel(const int* __restrict__ dst, int E) {
    int i = blockIdx.x * blockDim.x + threadIdx.x;
    if (i < E) atomicAdd(&g_cnt[dst[i]], 1);
}

// Single-block exclusive scan over g_cnt -> g_row, plus dinv, plus cnt reset.
__global__ void scan_kernel() {            // <<<1, 1024>>>
    __shared__ int warp_sums[32];
    __shared__ int s_carry;
    const int tid = threadIdx.x, lane = tid & 31, wid = tid >> 5;
    if (tid == 0) s_carry = 0;
    __syncthreads();
    for (int base = 0; base < N_NODES; base += 1024) {
        int i = base + tid;
        int v = (i < N_NODES) ? g_cnt[i] : 0;
        if (i < N_NODES) {
            g_dinv[i] = rsqrtf((float)v + 1.0f);   // +1 self-loop
            g_cnt[i] = 0;                           // reset as fill cursor
        }
        int x = v;
#pragma unroll
        for (int off = 1; off < 32; off <<= 1) {
            int t = __shfl_up_sync(0xffffffffu, x, off);
            if (lane >= off) x += t;
        }
        if (lane == 31) warp_sums[wid] = x;
        __syncthreads();
        if (wid == 0) {
            int y = warp_sums[lane];
#pragma unroll
            for (int off = 1; off < 32; off <<= 1) {
                int t = __shfl_up_sync(0xffffffffu, y, off);
                if (lane >= off) y += t;
            }
            warp_sums[lane] = y;
        }
        __syncthreads();
        int warp_off = (wid == 0) ? 0 : warp_sums[wid - 1];
        if (i < N_NODES) g_row[i] = s_carry + warp_off + x - v;   // exclusive
        __syncthreads();
        if (tid == 1023) s_carry += warp_sums[31];
        __syncthreads();
    }
    if (threadIdx.x == 0) g_row[N_NODES] = s_carry;
}

__global__ void fill_kernel(const int* __restrict__ src, const int* __restrict__ dst, int E) {
    int e = blockIdx.x * blockDim.x + threadIdx.x;
    if (e >= E) return;
    int s = src[e], d = dst[e];
    int pos = g_row[d] + atomicAdd(&g_cnt[d], 1);
    g_csr[pos] = make_int2(s, __float_as_int(g_dinv[s] * g_dinv[d]));
}

// ---------------- fp16 mma helper -------------------------------------------------
__device__ __forceinline__ void mma_f16(float* d, const uint32_t* a, uint32_t b0, uint32_t b1) {
    asm volatile(
        "mma.sync.aligned.m16n8k16.row.col.f32.f16.f16.f32 "
        "{%0,%1,%2,%3}, {%4,%5,%6,%7}, {%8,%9}, {%0,%1,%2,%3};"
        : "+f"(d[0]), "+f"(d[1]), "+f"(d[2]), "+f"(d[3])
        : "r"(a[0]), "r"(a[1]), "r"(a[2]), "r"(a[3]), "r"(b0), "r"(b1));
}

// ---------------- B fragment precompute ------------------------------------------
// m16n8k16 B fragment (col-major, B[k][n]): lane -> gid=lane>>2, tig=lane&3;
// b0 = {B[s*16+2tig][n], B[s*16+2tig+1][n]}, b1 = {B[s*16+8+2tig][n], B[+1][n]}.
// Stored: {bh0, bh1, bl0, bl1} where bh = fp16-hi pair, bl = fp16 residual pair.
template <int NKSTEP, int KDIM>
__device__ __forceinline__ void pack_bfrag(uint4* out, int i, float b00, float b01,
                                           float b10, float b11) {
    __half h00 = __float2half_rn(b00), h01 = __float2half_rn(b01);
    __half h10 = __float2half_rn(b10), h11 = __float2half_rn(b11);
    uint32_t bh0 = pack_h2(__half2float(h00), __half2float(h01));
    uint32_t bh1 = pack_h2(__half2float(h10), __half2float(h11));
    uint32_t bl0 = pack_h2(b00 - __half2float(h00), b01 - __half2float(h01));
    uint32_t bl1 = pack_h2(b10 - __half2float(h10), b11 - __half2float(h11));
    out[i] = make_uint4(bh0, bh1, bl0, bl1);
}

__global__ void pack_bfrag1_kernel(const float* __restrict__ W1) {
    int i = blockIdx.x * blockDim.x + threadIdx.x;   // 0 .. 16*16*32-1
    if (i >= 16 * 16 * 32) return;
    int lane = i & 31, nt = (i >> 5) & 15, s = i >> 9;
    int gid = lane >> 2, tig = lane & 3;
    int n = nt * 8 + gid;
    int k0 = s * 16 + 2 * tig;
    int k1 = k0 + 8;
    pack_bfrag<16, 256>(g_Bf1, i,
                        W1[(k0 + 0) * 128 + n], W1[(k0 + 1) * 128 + n],
                        W1[(k1 + 0) * 128 + n], W1[(k1 + 1) * 128 + n]);
}

__global__ void pack_bfrag2_kernel(const float* __restrict__ Wmu, const float* __restrict__ Wvar,
                                   const float* __restrict__ bmu, const float* __restrict__ bvar) {
    int i = blockIdx.x * blockDim.x + threadIdx.x;
    if (i < 128) g_bc[i] = (i < D_DIM) ? bmu[i] : bvar[i - D_DIM];
    if (i >= 8 * 16 * 32) return;
    int lane = i & 31, nt = (i >> 5) & 15, s = i >> 9;
    int gid = lane >> 2, tig = lane & 3;
    int n = nt * 8 + gid;
    int k0 = s * 16 + 2 * tig;
    int k1 = k0 + 8;
    auto W = [&](int k) {
        return (n < D_DIM) ? Wmu[k * D_DIM + n] : Wvar[k * D_DIM + (n - D_DIM)];
    };
    pack_bfrag<8, 128>(g_Bf2, i, W(k0), W(k0 + 1), W(k1), W(k1 + 1));
}

// ---------------- 2-split FP16 tensor-core GEMM: C[M,128] = A[M,K] @ B[K,128] -----
// Block 128x128, 256 threads = 8 warps as 2(m) x 4(n); warp tile 64x32.
// BK=16 double-buffered A in smem, half2-packed k-pairs at [kpair][row].
// A split: x = xh + xl (both fp16). D = Ah*Bh + Ah*Bl + Al*Bh (fp32 accum);
// dropped Al*Bl ~ 2^-22 relative. B fragments pre-split in global buffers.
// MODE 0: A = x -> g_h1 (fp16). MODE 1: A = g_agg2, +bias -> mu|sigma (fp32).
template <int MODE>
__global__ void __launch_bounds__(256, 2)
tgemm_kernel(const float* __restrict__ Ap,
             float* __restrict__ outMu, float* __restrict__ outSig,
             int M, int K) {
    __shared__ __align__(16) uint32_t Ah[2][8][136];   // [buf][kpair][row] f16x2
    __shared__ __align__(16) uint32_t Al[2][8][136];

    const float* A  = (MODE == 0) ? Ap : g_agg2;
    const uint4* Bf = (MODE == 0) ? g_Bf1 : g_Bf2;

    const int tid    = threadIdx.x;
    const int lane   = tid & 31;
    const int wid    = tid >> 5;
    const int warp_m = wid >> 2;      // 0..1 (64 rows each)
    const int warp_n = wid & 3;       // 0..3 (32 cols each)
    const int gid    = lane >> 2;     // 0..7
    const int tig    = lane & 3;      // 0..3
    const int row0   = blockIdx.x * 128;

    float acc[4][4][4];
#pragma unroll
    for (int mt = 0; mt < 4; mt++)
#pragma unroll
        for (int nt = 0; nt < 4; nt++)
#pragma unroll
            for (int r = 0; r < 4; r++) acc[mt][nt][r] = 0.0f;

    // BK=16 tile: each thread stages row r = tid>>1, k-octet q8 = (tid&1)*8.
    auto load_tile = [&](int k0, int buf) {
        int r = tid >> 1, q8 = (tid & 1) * 8;
        int gr = row0 + r;
        float4 va0 = make_float4(0.f, 0.f, 0.f, 0.f);
        float4 va1 = make_float4(0.f, 0.f, 0.f, 0.f);
        if (gr < M) {
            const float* ap = &A[(size_t)gr * K + k0 + q8];
            va0 = *(const float4*)&ap[0];
            va1 = *(const float4*)&ap[4];
        }
        float av[8] = {va0.x, va0.y, va0.z, va0.w, va1.x, va1.y, va1.z, va1.w};
        int kp0 = q8 >> 1;                       // 0 or 4
#pragma unroll
        for (int jp = 0; jp < 4; jp++) {
            float x0 = av[2 * jp], x1 = av[2 * jp + 1];
            __half h0 = __float2half_rn(x0), h1 = __float2half_rn(x1);
            Ah[buf][kp0 + jp][r] = pack_h2(__half2float(h0), __half2float(h1));
            Al[buf][kp0 + jp][r] = pack_h2(x0 - __half2float(h0), x1 - __half2float(h1));
        }
    };

    const int steps = K / 16;
    load_tile(0, 0);
    __syncthreads();

    const uint4* BfW = Bf + (size_t)warp_n * 4 * 32 + lane;   // + s*16*32 + nt*32

    for (int s = 0; s < steps; s++) {
        uint4 fb[4];
#pragma unroll
        for (int nt = 0; nt < 4; nt++)
            fb[nt] = __ldg(&BfW[(size_t)s * 16 * 32 + nt * 32]);

        if (s + 1 < steps) load_tile((s + 1) * 16, (s + 1) & 1);
        const int cb = s & 1;

        // A fragments: a0=row gid,k 2tig..+1 (kp=tig); a1=row gid+8; a2,a3: kp=tig+4
        uint32_t fah[4][4], fal[4][4];
#pragma unroll
        for (int mt = 0; mt < 4; mt++) {
            int m0 = warp_m * 64 + mt * 16;
            fah[mt][0] = Ah[cb][tig][m0 + gid];
            fah[mt][1] = Ah[cb][tig][m0 + 8 + gid];
            fah[mt][2] = Ah[cb][tig + 4][m0 + gid];
            fah[mt][3] = Ah[cb][tig + 4][m0 + 8 + gid];
            fal[mt][0] = Al[cb][tig][m0 + gid];
            fal[mt][1] = Al[cb][tig][m0 + 8 + gid];
            fal[mt][2] = Al[cb][tig + 4][m0 + gid];
            fal[mt][3] = Al[cb][tig + 4][m0 + 8 + gid];
        }
#pragma unroll
        for (int mt = 0; mt < 4; mt++)
#pragma unroll
            for (int nt = 0; nt < 4; nt++) {
                mma_f16(acc[mt][nt], fah[mt], fb[nt].x, fb[nt].y);   // Ah*Bh
                mma_f16(acc[mt][nt], fah[mt], fb[nt].z, fb[nt].w);   // Ah*Bl
                mma_f16(acc[mt][nt], fal[mt], fb[nt].x, fb[nt].y);   // Al*Bh
            }
        __syncthreads();
    }

    // Epilogue. c0,c1 -> row gid, cols 2tig,2tig+1; c2,c3 -> row gid+8.
#pragma unroll
    for (int mt = 0; mt < 4; mt++) {
#pragma unroll
        for (int nt = 0; nt < 4; nt++) {
            int col = warp_n * 32 + nt * 8 + 2 * tig;
            int ra  = row0 + warp_m * 64 + mt * 16 + gid;
            int rb  = ra + 8;
            if (MODE == 0) {
                if (ra < M) *(__half2*)&g_h1[(size_t)ra * 128 + col] =
                    __floats2half2_rn(acc[mt][nt][0], acc[mt][nt][1]);
                if (rb < M) *(__half2*)&g_h1[(size_t)rb * 128 + col] =
                    __floats2half2_rn(acc[mt][nt][2], acc[mt][nt][3]);
            } else {
                float b0 = g_bc[col], b1 = g_bc[col + 1];
                float* baseA;
                float* baseB;
                if (col < 64) {
                    baseA = outMu + (size_t)ra * D_DIM + col;
                    baseB = outMu + (size_t)rb * D_DIM + col;
                } else {
                    baseA = outSig + (size_t)ra * D_DIM + (col - 64);
                    baseB = outSig + (size_t)rb * D_DIM + (col - 64);
                }
                if (ra < M) *(float2*)baseA =
                    make_float2(acc[mt][nt][0] + b0, acc[mt][nt][1] + b1);
                if (rb < M) *(float2*)baseB =
                    make_float2(acc[mt][nt][2] + b0, acc[mt][nt][3] + b1);
            }
        }
    }
}

// ---------------- CSR gather-aggregate (fp16 h rows, fp32 accumulate) -------------
// One warp per node; each lane covers 4 features (8B fp16 load per row).
// LAYER 0: reads g_h1, writes g_h2 = relu(agg + b1) as fp16 (relu fused)
// LAYER 1: reads g_h2, writes g_agg2 as fp32 (feeds GEMM2).
template <int LAYER>
__global__ void __launch_bounds__(256)
aggregate_kernel(const float* __restrict__ b1) {
    int n    = (blockIdx.x * 256 + threadIdx.x) >> 5;
    int lane = threadIdx.x & 31;
    if (n >= N_NODES) return;

    const __half* h = (LAYER == 0) ? g_h1 : g_h2;

    float di = g_dinv[n];
    float d2 = di * di;
    float4 acc = h4_to_f4(((const uint2*)(h + (size_t)n * 128))[lane]);
    acc.x *= d2; acc.y *= d2; acc.z *= d2; acc.w *= d2;

    int r0 = g_row[n], r1 = g_row[n + 1];
    for (int base = r0; base < r1; base += 32) {
        int rem = min(r1 - base, 32);
        int2 ent = make_int2(0, 0);
        if (lane < rem) ent = g_csr[base + lane];

        int k = 0;
        for (; k + 4 <= rem; k += 4) {
            int   s0 = __shfl_sync(0xffffffffu, ent.x, k + 0);
            int   s1 = __shfl_sync(0xffffffffu, ent.x, k + 1);
            int   s2 = __shfl_sync(0xffffffffu, ent.x, k + 2);
            int   s3 = __shfl_sync(0xffffffffu, ent.x, k + 3);
            float w0 = __int_as_float(__shfl_sync(0xffffffffu, ent.y, k + 0));
            float w1 = __int_as_float(__shfl_sync(0xffffffffu, ent.y, k + 1));
            float w2 = __int_as_float(__shfl_sync(0xffffffffu, ent.y, k + 2));
            float w3 = __int_as_float(__shfl_sync(0xffffffffu, ent.y, k + 3));
            uint2 u0 = ((const uint2*)(h + (size_t)s0 * 128))[lane];
            uint2 u1 = ((const uint2*)(h + (size_t)s1 * 128))[lane];
            uint2 u2 = ((const uint2*)(h + (size_t)s2 * 128))[lane];
            uint2 u3 = ((const uint2*)(h + (size_t)s3 * 128))[lane];
            float4 v0 = h4_to_f4(u0);
            float4 v1 = h4_to_f4(u1);
            float4 v2 = h4_to_f4(u2);
            float4 v3 = h4_to_f4(u3);
            acc.x = fmaf(v0.x, w0, acc.x); acc.y = fmaf(v0.y, w0, acc.y);
            acc.z = fmaf(v0.z, w0, acc.z); acc.w = fmaf(v0.w, w0, acc.w);
            acc.x = fmaf(v1.x, w1, acc.x); acc.y = fmaf(v1.y, w1, acc.y);
            acc.z = fmaf(v1.z, w1, acc.z); acc.w = fmaf(v1.w, w1, acc.w);
            acc.x = fmaf(v2.x, w2, acc.x); acc.y = fmaf(v2.y, w2, acc.y);
            acc.z = fmaf(v2.z, w2, acc.z); acc.w = fmaf(v2.w, w2, acc.w);
            acc.x = fmaf(v3.x, w3, acc.x); acc.y = fmaf(v3.y, w3, acc.y);
            acc.z = fmaf(v3.z, w3, acc.z); acc.w = fmaf(v3.w, w3, acc.w);
        }
        for (; k < rem; k++) {
            int   s = __shfl_sync(0xffffffffu, ent.x, k);
            float w = __int_as_float(__shfl_sync(0xffffffffu, ent.y, k));
            float4 v = h4_to_f4(((const uint2*)(h + (size_t)s * 128))[lane]);
            acc.x = fmaf(v.x, w, acc.x); acc.y = fmaf(v.y, w, acc.y);
            acc.z = fmaf(v.z, w, acc.z); acc.w = fmaf(v.w, w, acc.w);
        }
    }

    if (LAYER == 0) {
        float4 b = ((const float4*)b1)[lane];
        acc.x = fmaxf(acc.x + b.x, 0.0f);
        acc.y = fmaxf(acc.y + b.y, 0.0f);
        acc.z = fmaxf(acc.z + b.z, 0.0f);
        acc.w = fmaxf(acc.w + b.w, 0.0f);
        ((uint2*)(g_h2 + (size_t)n * 128))[lane] = f4_to_h4(acc);
    } else {
        ((float4*)(g_agg2 + (size_t)n * 128))[lane] = acc;
    }
}

// --------------------------------------------------------------------------------
extern "C" void kernel_launch(void* const* d_in, const int* in_sizes, int n_in,
                              void* d_out, int out_size) {
    const float* x    = (const float*)d_in[0];
    const int*   ei   = (const int*)d_in[1];     // edge_index: int32
    const float* W1   = (const float*)d_in[2];
    const float* b1   = (const float*)d_in[3];
    const float* Wmu  = (const float*)d_in[4];
    const float* bmu  = (const float*)d_in[5];
    const float* Wvar = (const float*)d_in[6];
    const float* bvar = (const float*)d_in[7];

    const int E = in_sizes[1] / 2;
    const int* src = ei;
    const int* dst = ei + E;

    float* outMu  = (float*)d_out;
    float* outSig = (float*)d_out + (size_t)N_NODES * D_DIM;

    const int aggBlocks = (N_NODES * 32 + 255) / 256;   // one warp per node

    // 1-3: CSR counts + W1 fragment pack
    zero_cnt_kernel <<<(N_NODES + 255) / 256, 256>>>();
    count_kernel    <<<(E + 255) / 256, 256>>>(dst, E);
    pack_bfrag1_kernel<<<(16 * 16 * 32 + 255) / 256, 256>>>(W1);

    // 4: layer-1 fp16 GEMM (h1, fp16 out) — ncu capture slot
    tgemm_kernel<0><<<(N_NODES + 127) / 128, 256>>>(x, nullptr, nullptr, N_NODES, F_IN);

    // 5-6: scan + CSR fill
    scan_kernel<<<1, 1024>>>();
    fill_kernel<<<(E + 255) / 256, 256>>>(src, dst, E);

    // 7: layer-1 aggregate + fused relu (writes h2, fp16)
    aggregate_kernel<0><<<aggBlocks, 256>>>(b1);

    // 8: layer-2 aggregate (agg2, fp32)
    aggregate_kernel<1><<<aggBlocks, 256>>>(nullptr);

    // 9: pack projection fragments + bias
    pack_bfrag2_kernel<<<(8 * 16 * 32 + 255) / 256, 256>>>(Wmu, Wvar, bmu, bvar);

    // 10: fused mu/sigma fp16 GEMM into d_out
    tgemm_kernel<1><<<(N_NODES + 127) / 128, 256>>>(nullptr, outMu, outSig, N_NODES, H_DIM);
}

// round 14
// speedup vs baseline: 2.4873x; 1.1306x over previous
#include <cuda_runtime.h>
#include <cuda_fp16.h>
#include <cstdint>

// Problem constants (fixed shapes per reference)
#define N_NODES 100000
#define F_IN    256
#define H_DIM   128
#define D_DIM   64
#define MAX_E   1700000

// ---------------- scratch (device globals; no allocation allowed) -------------
__device__ __align__(16) int    g_cnt [N_NODES];             // per-dst edge count / fill cursor
__device__ __align__(16) int    g_row [N_NODES + 1];         // CSR row offsets
__device__ __align__(16) float  g_dinv[N_NODES];             // rsqrt(deg) incl self-loop
__device__ __align__(16) int2   g_csr [MAX_E];               // {src, norm-as-int-bits}
__device__ __align__(16) __half g_h1  [N_NODES * H_DIM];     // x @ W1        (fp16 storage)
__device__ __align__(16) __half g_h2  [N_NODES * H_DIM];     // relu(agg1+b1) (fp16 storage)
__device__ __align__(16) float  g_agg2[N_NODES * H_DIM];     // aggregated h2 (fp32)
__device__ __align__(16) float  g_bc  [128];                 // [bmu | bvar]
// Precomputed B fragments for m16n8k16 fp16 mma (2-split hi/lo):
//   index = (kstep16*16 + ntile)*32 + lane, value = {bh0, bh1, bl0, bl1} (f16x2 each)
__device__ __align__(16) uint4 g_Bf1[16 * 16 * 32];          // W1:  K=256 -> 16 ksteps
__device__ __align__(16) uint4 g_Bf2[ 8 * 16 * 32];          // Wc:  K=128 ->  8 ksteps

// ---------------- fp16 pack/unpack helpers ---------------------------------------
__device__ __forceinline__ float4 h4_to_f4(uint2 u) {
    float2 f0 = __half22float2(*(const __half2*)&u.x);
    float2 f1 = __half22float2(*(const __half2*)&u.y);
    return make_float4(f0.x, f0.y, f1.x, f1.y);
}
__device__ __forceinline__ uint2 f4_to_h4(float4 v) {
    __half2 h0 = __floats2half2_rn(v.x, v.y);
    __half2 h1 = __floats2half2_rn(v.z, v.w);
    uint2 u;
    u.x = *(const uint32_t*)&h0;
    u.y = *(const uint32_t*)&h1;
    return u;
}
__device__ __forceinline__ uint32_t pack_h2(float x, float y) {
    __half2 h = __floats2half2_rn(x, y);
    return *(const uint32_t*)&h;
}

// ---------------- CSR build ------------------------------------------------------
__global__ void zero_cnt_kernel() {
    int i = blockIdx.x * blockDim.x + threadIdx.x;
    if (i < N_NODES) g_cnt[i] = 0;
}

__global__ void count_kernel(const int* __restrict__ dst, int E) {
    int i = blockIdx.x * blockDim.x + threadIdx.x;
    if (i < E) atomicAdd(&g_cnt[dst[i]], 1);
}

// Single-block exclusive scan over g_cnt -> g_row, plus dinv, plus cnt reset.
__global__ void scan_kernel() {            // <<<1, 1024>>>
    __shared__ int warp_sums[32];
    __shared__ int s_carry;
    const int tid = threadIdx.x, lane = tid & 31, wid = tid >> 5;
    if (tid == 0) s_carry = 0;
    __syncthreads();
    for (int base = 0; base < N_NODES; base += 1024) {
        int i = base + tid;
        int v = (i < N_NODES) ? g_cnt[i] : 0;
        if (i < N_NODES) {
            g_dinv[i] = rsqrtf((float)v + 1.0f);   // +1 self-loop
            g_cnt[i] = 0;                           // reset as fill cursor
        }
        int x = v;
#pragma unroll
        for (int off = 1; off < 32; off <<= 1) {
            int t = __shfl_up_sync(0xffffffffu, x, off);
            if (lane >= off) x += t;
        }
        if (lane == 31) warp_sums[wid] = x;
        __syncthreads();
        if (wid == 0) {
            int y = warp_sums[lane];
#pragma unroll
            for (int off = 1; off < 32; off <<= 1) {
                int t = __shfl_up_sync(0xffffffffu, y, off);
                if (lane >= off) y += t;
            }
            warp_sums[lane] = y;
        }
        __syncthreads();
        int warp_off = (wid == 0) ? 0 : warp_sums[wid - 1];
        if (i < N_NODES) g_row[i] = s_carry + warp_off + x - v;   // exclusive
        __syncthreads();
        if (tid == 1023) s_carry += warp_sums[31];
        __syncthreads();
    }
    if (threadIdx.x == 0) g_row[N_NODES] = s_carry;
}

__global__ void fill_kernel(const int* __restrict__ src, const int* __restrict__ dst, int E) {
    int e = blockIdx.x * blockDim.x + threadIdx.x;
    if (e >= E) return;
    int s = src[e], d = dst[e];
    int pos = g_row[d] + atomicAdd(&g_cnt[d], 1);
    g_csr[pos] = make_int2(s, __float_as_int(g_dinv[s] * g_dinv[d]));
}

// ---------------- fp16 mma helper -------------------------------------------------
__device__ __forceinline__ void mma_f16(float* d, const uint32_t* a, uint32_t b0, uint32_t b1) {
    asm volatile(
        "mma.sync.aligned.m16n8k16.row.col.f32.f16.f16.f32 "
        "{%0,%1,%2,%3}, {%4,%5,%6,%7}, {%8,%9}, {%0,%1,%2,%3};"
        : "+f"(d[0]), "+f"(d[1]), "+f"(d[2]), "+f"(d[3])
        : "r"(a[0]), "r"(a[1]), "r"(a[2]), "r"(a[3]), "r"(b0), "r"(b1));
}

// ---------------- B fragment precompute ------------------------------------------
// m16n8k16 B fragment (col-major, B[k][n]): lane -> gid=lane>>2, tig=lane&3;
// b0 = {B[s*16+2tig][n], B[s*16+2tig+1][n]}, b1 = {B[s*16+8+2tig][n], B[+1][n]}.
// Stored: {bh0, bh1, bl0, bl1} where bh = fp16-hi pair, bl = fp16 residual pair.
__device__ __forceinline__ void pack_bfrag(uint4* out, int i, float b00, float b01,
                                           float b10, float b11) {
    __half h00 = __float2half_rn(b00), h01 = __float2half_rn(b01);
    __half h10 = __float2half_rn(b10), h11 = __float2half_rn(b11);
    uint32_t bh0 = pack_h2(__half2float(h00), __half2float(h01));
    uint32_t bh1 = pack_h2(__half2float(h10), __half2float(h11));
    uint32_t bl0 = pack_h2(b00 - __half2float(h00), b01 - __half2float(h01));
    uint32_t bl1 = pack_h2(b10 - __half2float(h10), b11 - __half2float(h11));
    out[i] = make_uint4(bh0, bh1, bl0, bl1);
}

__global__ void pack_bfrag1_kernel(const float* __restrict__ W1) {
    int i = blockIdx.x * blockDim.x + threadIdx.x;   // 0 .. 16*16*32-1
    if (i >= 16 * 16 * 32) return;
    int lane = i & 31, nt = (i >> 5) & 15, s = i >> 9;
    int gid = lane >> 2, tig = lane & 3;
    int n = nt * 8 + gid;
    int k0 = s * 16 + 2 * tig;
    int k1 = k0 + 8;
    pack_bfrag(g_Bf1, i,
               W1[(k0 + 0) * 128 + n], W1[(k0 + 1) * 128 + n],
               W1[(k1 + 0) * 128 + n], W1[(k1 + 1) * 128 + n]);
}

__global__ void pack_bfrag2_kernel(const float* __restrict__ Wmu, const float* __restrict__ Wvar,
                                   const float* __restrict__ bmu, const float* __restrict__ bvar) {
    int i = blockIdx.x * blockDim.x + threadIdx.x;
    if (i < 128) g_bc[i] = (i < D_DIM) ? bmu[i] : bvar[i - D_DIM];
    if (i >= 8 * 16 * 32) return;
    int lane = i & 31, nt = (i >> 5) & 15, s = i >> 9;
    int gid = lane >> 2, tig = lane & 3;
    int n = nt * 8 + gid;
    int k0 = s * 16 + 2 * tig;
    int k1 = k0 + 8;
    auto W = [&](int k) {
        return (n < D_DIM) ? Wmu[k * D_DIM + n] : Wvar[k * D_DIM + (n - D_DIM)];
    };
    pack_bfrag(g_Bf2, i, W(k0), W(k0 + 1), W(k1), W(k1 + 1));
}

// ---------------- 2-split FP16 tensor-core GEMM: C[M,128] = A[M,K] @ B[K,128] -----
// Block 128x128, 256 threads = 8 warps as 2(m) x 4(n); warp tile 64x32.
// BK=16 double-buffered A in smem, half2-packed k-pairs at [kpair][row].
// A split: x = xh + xl (both fp16). D = Ah*Bh + Ah*Bl + Al*Bh (fp32 accum);
// dropped Al*Bl ~ 2^-22 relative. B fragments pre-split in global buffers.
// MODE 0: A = x -> g_h1 (fp16). MODE 1: A = g_agg2, +bias -> mu|sigma (fp32).
template <int MODE>
__global__ void __launch_bounds__(256, 2)
tgemm_kernel(const float* __restrict__ Ap,
             float* __restrict__ outMu, float* __restrict__ outSig,
             int M, int K) {
    __shared__ __align__(16) uint32_t Ah[2][8][136];   // [buf][kpair][row] f16x2
    __shared__ __align__(16) uint32_t Al[2][8][136];

    const float* A  = (MODE == 0) ? Ap : g_agg2;
    const uint4* Bf = (MODE == 0) ? g_Bf1 : g_Bf2;

    const int tid    = threadIdx.x;
    const int lane   = tid & 31;
    const int wid    = tid >> 5;
    const int warp_m = wid >> 2;      // 0..1 (64 rows each)
    const int warp_n = wid & 3;       // 0..3 (32 cols each)
    const int gid    = lane >> 2;     // 0..7
    const int tig    = lane & 3;      // 0..3
    const int row0   = blockIdx.x * 128;

    float acc[4][4][4];
#pragma unroll
    for (int mt = 0; mt < 4; mt++)
#pragma unroll
        for (int nt = 0; nt < 4; nt++)
#pragma unroll
            for (int r = 0; r < 4; r++) acc[mt][nt][r] = 0.0f;

    // BK=16 tile: each thread stages row r = tid>>1, k-octet q8 = (tid&1)*8.
    auto load_tile = [&](int k0, int buf) {
        int r = tid >> 1, q8 = (tid & 1) * 8;
        int gr = row0 + r;
        float4 va0 = make_float4(0.f, 0.f, 0.f, 0.f);
        float4 va1 = make_float4(0.f, 0.f, 0.f, 0.f);
        if (gr < M) {
            const float* ap = &A[(size_t)gr * K + k0 + q8];
            va0 = *(const float4*)&ap[0];
            va1 = *(const float4*)&ap[4];
        }
        float av[8] = {va0.x, va0.y, va0.z, va0.w, va1.x, va1.y, va1.z, va1.w};
        int kp0 = q8 >> 1;                       // 0 or 4
#pragma unroll
        for (int jp = 0; jp < 4; jp++) {
            float x0 = av[2 * jp], x1 = av[2 * jp + 1];
            __half h0 = __float2half_rn(x0), h1 = __float2half_rn(x1);
            Ah[buf][kp0 + jp][r] = pack_h2(__half2float(h0), __half2float(h1));
            Al[buf][kp0 + jp][r] = pack_h2(x0 - __half2float(h0), x1 - __half2float(h1));
        }
    };

    const int steps = K / 16;
    load_tile(0, 0);
    __syncthreads();

    const uint4* BfW = Bf + (size_t)warp_n * 4 * 32 + lane;   // + s*16*32 + nt*32

    for (int s = 0; s < steps; s++) {
        uint4 fb[4];
#pragma unroll
        for (int nt = 0; nt < 4; nt++)
            fb[nt] = __ldg(&BfW[(size_t)s * 16 * 32 + nt * 32]);

        if (s + 1 < steps) load_tile((s + 1) * 16, (s + 1) & 1);
        const int cb = s & 1;

        uint32_t fah[4][4], fal[4][4];
#pragma unroll
        for (int mt = 0; mt < 4; mt++) {
            int m0 = warp_m * 64 + mt * 16;
            fah[mt][0] = Ah[cb][tig][m0 + gid];
            fah[mt][1] = Ah[cb][tig][m0 + 8 + gid];
            fah[mt][2] = Ah[cb][tig + 4][m0 + gid];
            fah[mt][3] = Ah[cb][tig + 4][m0 + 8 + gid];
            fal[mt][0] = Al[cb][tig][m0 + gid];
            fal[mt][1] = Al[cb][tig][m0 + 8 + gid];
            fal[mt][2] = Al[cb][tig + 4][m0 + gid];
            fal[mt][3] = Al[cb][tig + 4][m0 + 8 + gid];
        }
#pragma unroll
        for (int mt = 0; mt < 4; mt++)
#pragma unroll
            for (int nt = 0; nt < 4; nt++) {
                mma_f16(acc[mt][nt], fah[mt], fb[nt].x, fb[nt].y);   // Ah*Bh
                mma_f16(acc[mt][nt], fah[mt], fb[nt].z, fb[nt].w);   // Ah*Bl
                mma_f16(acc[mt][nt], fal[mt], fb[nt].x, fb[nt].y);   // Al*Bh
            }
        __syncthreads();
    }

    // Epilogue. c0,c1 -> row gid, cols 2tig,2tig+1; c2,c3 -> row gid+8.
#pragma unroll
    for (int mt = 0; mt < 4; mt++) {
#pragma unroll
        for (int nt = 0; nt < 4; nt++) {
            int col = warp_n * 32 + nt * 8 + 2 * tig;
            int ra  = row0 + warp_m * 64 + mt * 16 + gid;
            int rb  = ra + 8;
            if (MODE == 0) {
                if (ra < M) *(__half2*)&g_h1[(size_t)ra * 128 + col] =
                    __floats2half2_rn(acc[mt][nt][0], acc[mt][nt][1]);
                if (rb < M) *(__half2*)&g_h1[(size_t)rb * 128 + col] =
                    __floats2half2_rn(acc[mt][nt][2], acc[mt][nt][3]);
            } else {
                float b0 = g_bc[col], b1 = g_bc[col + 1];
                float* baseA;
                float* baseB;
                if (col < 64) {
                    baseA = outMu + (size_t)ra * D_DIM + col;
                    baseB = outMu + (size_t)rb * D_DIM + col;
                } else {
                    baseA = outSig + (size_t)ra * D_DIM + (col - 64);
                    baseB = outSig + (size_t)rb * D_DIM + (col - 64);
                }
                if (ra < M) *(float2*)baseA =
                    make_float2(acc[mt][nt][0] + b0, acc[mt][nt][1] + b1);
                if (rb < M) *(float2*)baseB =
                    make_float2(acc[mt][nt][2] + b0, acc[mt][nt][3] + b1);
            }
        }
    }
}

// ---------------- CSR gather-aggregate (fp16 h rows, fp32 accumulate) -------------
// One warp per node; each lane covers 4 features (8B fp16 load per row).
// LAYER 0: reads g_h1, writes g_h2 = relu(agg + b1) as fp16 (relu fused)
// LAYER 1: reads g_h2, writes g_agg2 as fp32 (feeds GEMM2).
template <int LAYER>
__global__ void __launch_bounds__(256)
aggregate_kernel(const float* __restrict__ b1) {
    int n    = (blockIdx.x * 256 + threadIdx.x) >> 5;
    int lane = threadIdx.x & 31;
    if (n >= N_NODES) return;

    const __half* h = (LAYER == 0) ? g_h1 : g_h2;

    float di = g_dinv[n];
    float d2 = di * di;
    float4 acc = h4_to_f4(((const uint2*)(h + (size_t)n * 128))[lane]);
    acc.x *= d2; acc.y *= d2; acc.z *= d2; acc.w *= d2;

    int r0 = g_row[n], r1 = g_row[n + 1];
    for (int base = r0; base < r1; base += 32) {
        int rem = min(r1 - base, 32);
        int2 ent = make_int2(0, 0);
        if (lane < rem) ent = g_csr[base + lane];

        int k = 0;
        for (; k + 4 <= rem; k += 4) {
            int   s0 = __shfl_sync(0xffffffffu, ent.x, k + 0);
            int   s1 = __shfl_sync(0xffffffffu, ent.x, k + 1);
            int   s2 = __shfl_sync(0xffffffffu, ent.x, k + 2);
            int   s3 = __shfl_sync(0xffffffffu, ent.x, k + 3);
            float w0 = __int_as_float(__shfl_sync(0xffffffffu, ent.y, k + 0));
            float w1 = __int_as_float(__shfl_sync(0xffffffffu, ent.y, k + 1));
            float w2 = __int_as_float(__shfl_sync(0xffffffffu, ent.y, k + 2));
            float w3 = __int_as_float(__shfl_sync(0xffffffffu, ent.y, k + 3));
            uint2 u0 = ((const uint2*)(h + (size_t)s0 * 128))[lane];
            uint2 u1 = ((const uint2*)(h + (size_t)s1 * 128))[lane];
            uint2 u2 = ((const uint2*)(h + (size_t)s2 * 128))[lane];
            uint2 u3 = ((const uint2*)(h + (size_t)s3 * 128))[lane];
            float4 v0 = h4_to_f4(u0);
            float4 v1 = h4_to_f4(u1);
            float4 v2 = h4_to_f4(u2);
            float4 v3 = h4_to_f4(u3);
            acc.x = fmaf(v0.x, w0, acc.x); acc.y = fmaf(v0.y, w0, acc.y);
            acc.z = fmaf(v0.z, w0, acc.z); acc.w = fmaf(v0.w, w0, acc.w);
            acc.x = fmaf(v1.x, w1, acc.x); acc.y = fmaf(v1.y, w1, acc.y);
            acc.z = fmaf(v1.z, w1, acc.z); acc.w = fmaf(v1.w, w1, acc.w);
            acc.x = fmaf(v2.x, w2, acc.x); acc.y = fmaf(v2.y, w2, acc.y);
            acc.z = fmaf(v2.z, w2, acc.z); acc.w = fmaf(v2.w, w2, acc.w);
            acc.x = fmaf(v3.x, w3, acc.x); acc.y = fmaf(v3.y, w3, acc.y);
            acc.z = fmaf(v3.z, w3, acc.z); acc.w = fmaf(v3.w, w3, acc.w);
        }
        for (; k < rem; k++) {
            int   s = __shfl_sync(0xffffffffu, ent.x, k);
            float w = __int_as_float(__shfl_sync(0xffffffffu, ent.y, k));
            float4 v = h4_to_f4(((const uint2*)(h + (size_t)s * 128))[lane]);
            acc.x = fmaf(v.x, w, acc.x); acc.y = fmaf(v.y, w, acc.y);
            acc.z = fmaf(v.z, w, acc.z); acc.w = fmaf(v.w, w, acc.w);
        }
    }

    if (LAYER == 0) {
        float4 b = ((const float4*)b1)[lane];
        acc.x = fmaxf(acc.x + b.x, 0.0f);
        acc.y = fmaxf(acc.y + b.y, 0.0f);
        acc.z = fmaxf(acc.z + b.z, 0.0f);
        acc.w = fmaxf(acc.w + b.w, 0.0f);
        ((uint2*)(g_h2 + (size_t)n * 128))[lane] = f4_to_h4(acc);
    } else {
        ((float4*)(g_agg2 + (size_t)n * 128))[lane] = acc;
    }
}

// --------------------------------------------------------------------------------
extern "C" void kernel_launch(void* const* d_in, const int* in_sizes, int n_in,
                              void* d_out, int out_size) {
    const float* x    = (const float*)d_in[0];
    const int*   ei   = (const int*)d_in[1];     // edge_index: int32
    const float* W1   = (const float*)d_in[2];
    const float* b1   = (const float*)d_in[3];
    const float* Wmu  = (const float*)d_in[4];
    const float* bmu  = (const float*)d_in[5];
    const float* Wvar = (const float*)d_in[6];
    const float* bvar = (const float*)d_in[7];

    const int E = in_sizes[1] / 2;
    const int* src = ei;
    const int* dst = ei + E;

    float* outMu  = (float*)d_out;
    float* outSig = (float*)d_out + (size_t)N_NODES * D_DIM;

    const int aggBlocks = (N_NODES * 32 + 255) / 256;   // one warp per node

    // Side stream + fork/join events: created once, reused every call (the
    // captured graph is identical call-to-call; no device memory involved).
    static cudaStream_t s_csr = nullptr;
    static cudaEvent_t  s_evFork = nullptr, s_evJoin = nullptr;
    if (s_csr == nullptr) {
        cudaStreamCreateWithFlags(&s_csr, cudaStreamNonBlocking);
        cudaEventCreateWithFlags(&s_evFork, cudaEventDisableTiming);
        cudaEventCreateWithFlags(&s_evJoin, cudaEventDisableTiming);
    }

    // Fork: CSR chain + projection pack on side stream, GEMM1 on main stream.
    cudaEventRecord(s_evFork, 0);
    cudaStreamWaitEvent(s_csr, s_evFork, 0);

    pack_bfrag1_kernel<<<(16 * 16 * 32 + 255) / 256, 256>>>(W1);          // #1 main
    zero_cnt_kernel   <<<(N_NODES + 255) / 256, 256, 0, s_csr>>>();       // #2 side
    count_kernel      <<<(E + 255) / 256, 256, 0, s_csr>>>(dst, E);       // #3 side

    // #4 (ncu capture slot): layer-1 fp16 GEMM (h1) — overlaps the CSR chain
    tgemm_kernel<0><<<(N_NODES + 127) / 128, 256>>>(x, nullptr, nullptr, N_NODES, F_IN);

    scan_kernel       <<<1, 1024, 0, s_csr>>>();                          // #5 side
    fill_kernel       <<<(E + 255) / 256, 256, 0, s_csr>>>(src, dst, E);  // #6 side
    pack_bfrag2_kernel<<<(8 * 16 * 32 + 255) / 256, 256, 0, s_csr>>>(Wmu, Wvar, bmu, bvar);

    // Join: aggregates need both h1 (main) and CSR (side).
    cudaEventRecord(s_evJoin, s_csr);
    cudaStreamWaitEvent(0, s_evJoin, 0);

    // layer-1 aggregate + fused relu (writes h2, fp16)
    aggregate_kernel<0><<<aggBlocks, 256>>>(b1);

    // layer-2 aggregate (agg2, fp32)
    aggregate_kernel<1><<<aggBlocks, 256>>>(nullptr);

    // fused mu/sigma fp16 GEMM into d_out
    tgemm_kernel<1><<<(N_NODES + 127) / 128, 256>>>(nullptr, outMu, outSig, N_NODES, H_DIM);
}

// round 15
// speedup vs baseline: 2.5809x; 1.0376x over previous
#include <cuda_runtime.h>
#include <cuda_fp16.h>
#include <cstdint>

// Problem constants (fixed shapes per reference)
#define N_NODES 100000
#define F_IN    256
#define H_DIM   128
#define D_DIM   64
#define MAX_E   1700000

// ---------------- scratch (device globals; no allocation allowed) -------------
__device__ __align__(16) int    g_cnt [N_NODES];             // per-dst edge count / fill cursor
__device__ __align__(16) int    g_row [N_NODES + 1];         // CSR row offsets
__device__ __align__(16) float  g_dinv[N_NODES];             // rsqrt(deg) incl self-loop
__device__ __align__(16) int2   g_csr [MAX_E];               // {src, norm-as-int-bits}
__device__ __align__(16) __half g_h1  [N_NODES * H_DIM];     // x @ W1        (fp16)
__device__ __align__(16) __half g_h2  [N_NODES * H_DIM];     // relu(agg1+b1) (fp16)
__device__ __align__(16) __half g_agg2[N_NODES * H_DIM];     // aggregated h2 (fp16)
__device__ __align__(16) float  g_bc  [128];                 // [bmu | bvar]
// Precomputed B fragments for m16n8k16 fp16 mma (2-split hi/lo):
//   index = (kstep16*16 + ntile)*32 + lane, value = {bh0, bh1, bl0, bl1} (f16x2 each)
__device__ __align__(16) uint4 g_Bf1[16 * 16 * 32];          // W1:  K=256 -> 16 ksteps
__device__ __align__(16) uint4 g_Bf2[ 8 * 16 * 32];          // Wc:  K=128 ->  8 ksteps

// ---------------- fp16 pack/unpack helpers ---------------------------------------
__device__ __forceinline__ float4 h4_to_f4(uint2 u) {
    float2 f0 = __half22float2(*(const __half2*)&u.x);
    float2 f1 = __half22float2(*(const __half2*)&u.y);
    return make_float4(f0.x, f0.y, f1.x, f1.y);
}
__device__ __forceinline__ uint2 f4_to_h4(float4 v) {
    __half2 h0 = __floats2half2_rn(v.x, v.y);
    __half2 h1 = __floats2half2_rn(v.z, v.w);
    uint2 u;
    u.x = *(const uint32_t*)&h0;
    u.y = *(const uint32_t*)&h1;
    return u;
}
__device__ __forceinline__ uint32_t pack_h2(float x, float y) {
    __half2 h = __floats2half2_rn(x, y);
    return *(const uint32_t*)&h;
}

// ---------------- CSR build ------------------------------------------------------
__global__ void zero_cnt_kernel() {
    int i = blockIdx.x * blockDim.x + threadIdx.x;
    if (i < N_NODES) g_cnt[i] = 0;
}

__global__ void count_kernel(const int* __restrict__ dst, int E) {
    int i = blockIdx.x * blockDim.x + threadIdx.x;
    if (i < E) atomicAdd(&g_cnt[dst[i]], 1);
}

// Single-block exclusive scan over g_cnt -> g_row, plus dinv, plus cnt reset.
__global__ void scan_kernel() {            // <<<1, 1024>>>
    __shared__ int warp_sums[32];
    __shared__ int s_carry;
    const int tid = threadIdx.x, lane = tid & 31, wid = tid >> 5;
    if (tid == 0) s_carry = 0;
    __syncthreads();
    for (int base = 0; base < N_NODES; base += 1024) {
        int i = base + tid;
        int v = (i < N_NODES) ? g_cnt[i] : 0;
        if (i < N_NODES) {
            g_dinv[i] = rsqrtf((float)v + 1.0f);   // +1 self-loop
            g_cnt[i] = 0;                           // reset as fill cursor
        }
        int x = v;
#pragma unroll
        for (int off = 1; off < 32; off <<= 1) {
            int t = __shfl_up_sync(0xffffffffu, x, off);
            if (lane >= off) x += t;
        }
        if (lane == 31) warp_sums[wid] = x;
        __syncthreads();
        if (wid == 0) {
            int y = warp_sums[lane];
#pragma unroll
            for (int off = 1; off < 32; off <<= 1) {
                int t = __shfl_up_sync(0xffffffffu, y, off);
                if (lane >= off) y += t;
            }
            warp_sums[lane] = y;
        }
        __syncthreads();
        int warp_off = (wid == 0) ? 0 : warp_sums[wid - 1];
        if (i < N_NODES) g_row[i] = s_carry + warp_off + x - v;   // exclusive
        __syncthreads();
        if (tid == 1023) s_carry += warp_sums[31];
        __syncthreads();
    }
    if (threadIdx.x == 0) g_row[N_NODES] = s_carry;
}

__global__ void fill_kernel(const int* __restrict__ src, const int* __restrict__ dst, int E) {
    int e = blockIdx.x * blockDim.x + threadIdx.x;
    if (e >= E) return;
    int s = src[e], d = dst[e];
    int pos = g_row[d] + atomicAdd(&g_cnt[d], 1);
    g_csr[pos] = make_int2(s, __float_as_int(g_dinv[s] * g_dinv[d]));
}

// ---------------- fp16 mma + ldmatrix helpers -------------------------------------
__device__ __forceinline__ void mma_f16(float* d, const uint32_t* a, uint32_t b0, uint32_t b1) {
    asm volatile(
        "mma.sync.aligned.m16n8k16.row.col.f32.f16.f16.f32 "
        "{%0,%1,%2,%3}, {%4,%5,%6,%7}, {%8,%9}, {%0,%1,%2,%3};"
        : "+f"(d[0]), "+f"(d[1]), "+f"(d[2]), "+f"(d[3])
        : "r"(a[0]), "r"(a[1]), "r"(a[2]), "r"(a[3]), "r"(b0), "r"(b1));
}

__device__ __forceinline__ void ldsm_x4(uint32_t* d, const uint32_t* smem_ptr) {
    uint32_t addr = (uint32_t)__cvta_generic_to_shared(smem_ptr);
    asm volatile(
        "ldmatrix.sync.aligned.m8n8.x4.shared.b16 {%0,%1,%2,%3}, [%4];"
        : "=r"(d[0]), "=r"(d[1]), "=r"(d[2]), "=r"(d[3])
        : "r"(addr));
}

// ---------------- B fragment precompute ------------------------------------------
// m16n8k16 B fragment (col-major, B[k][n]): lane -> gid=lane>>2, tig=lane&3;
// b0 = {B[s*16+2tig][n], B[s*16+2tig+1][n]}, b1 = {B[s*16+8+2tig][n], B[+1][n]}.
__device__ __forceinline__ void pack_bfrag(uint4* out, int i, float b00, float b01,
                                           float b10, float b11) {
    __half h00 = __float2half_rn(b00), h01 = __float2half_rn(b01);
    __half h10 = __float2half_rn(b10), h11 = __float2half_rn(b11);
    uint32_t bh0 = pack_h2(__half2float(h00), __half2float(h01));
    uint32_t bh1 = pack_h2(__half2float(h10), __half2float(h11));
    uint32_t bl0 = pack_h2(b00 - __half2float(h00), b01 - __half2float(h01));
    uint32_t bl1 = pack_h2(b10 - __half2float(h10), b11 - __half2float(h11));
    out[i] = make_uint4(bh0, bh1, bl0, bl1);
}

__global__ void pack_bfrag1_kernel(const float* __restrict__ W1) {
    int i = blockIdx.x * blockDim.x + threadIdx.x;   // 0 .. 16*16*32-1
    if (i >= 16 * 16 * 32) return;
    int lane = i & 31, nt = (i >> 5) & 15, s = i >> 9;
    int gid = lane >> 2, tig = lane & 3;
    int n = nt * 8 + gid;
    int k0 = s * 16 + 2 * tig;
    int k1 = k0 + 8;
    pack_bfrag(g_Bf1, i,
               W1[(k0 + 0) * 128 + n], W1[(k0 + 1) * 128 + n],
               W1[(k1 + 0) * 128 + n], W1[(k1 + 1) * 128 + n]);
}

__global__ void pack_bfrag2_kernel(const float* __restrict__ Wmu, const float* __restrict__ Wvar,
                                   const float* __restrict__ bmu, const float* __restrict__ bvar) {
    int i = blockIdx.x * blockDim.x + threadIdx.x;
    if (i < 128) g_bc[i] = (i < D_DIM) ? bmu[i] : bvar[i - D_DIM];
    if (i >= 8 * 16 * 32) return;
    int lane = i & 31, nt = (i >> 5) & 15, s = i >> 9;
    int gid = lane >> 2, tig = lane & 3;
    int n = nt * 8 + gid;
    int k0 = s * 16 + 2 * tig;
    int k1 = k0 + 8;
    auto W = [&](int k) {
        return (n < D_DIM) ? Wmu[k * D_DIM + n] : Wvar[k * D_DIM + (n - D_DIM)];
    };
    pack_bfrag(g_Bf2, i, W(k0), W(k0 + 1), W(k1), W(k1 + 1));
}

// ---------------- 2-split FP16 tensor-core GEMM: C[M,128] = A[M,K] @ B[K,128] -----
// Block 128x128, 256 threads = 8 warps as 2(m) x 4(n); warp tile 64x32.
// BK=16 double-buffered A in smem, ROW-MAJOR [row][kpair] stride 12 words
// (8 kpairs + 4 pad: all 8 rows of an LDSM phase land in disjoint banks).
// Fragments loaded via ldmatrix.x4 (8 LDSM/warp-step vs 32 scalar LDS/thread).
// MODE 0: A = x (fp32, 2-split: Ah+Al, 3 mma) -> g_h1 (fp16).
// MODE 1: A = g_agg2 (fp16 exact: Al=0, 2 mma), +bias -> mu|sigma (fp32).
#define ASTRIDE 12
template <int MODE>
__global__ void __launch_bounds__(256, 2)
tgemm_kernel(const float* __restrict__ Ap,
             float* __restrict__ outMu, float* __restrict__ outSig,
             int M, int K) {
    __shared__ __align__(16) uint32_t Ah[2][128][ASTRIDE];   // f16x2 kpairs
    __shared__ __align__(16) uint32_t Al[2][128][ASTRIDE];   // MODE 0 only

    const uint4* Bf = (MODE == 0) ? g_Bf1 : g_Bf2;

    const int tid    = threadIdx.x;
    const int lane   = tid & 31;
    const int wid    = tid >> 5;
    const int warp_m = wid >> 2;      // 0..1 (64 rows each)
    const int warp_n = wid & 3;       // 0..3 (32 cols each)
    const int gid    = lane >> 2;     // 0..7
    const int tig    = lane & 3;      // 0..3
    const int row0   = blockIdx.x * 128;

    float acc[4][4][4];
#pragma unroll
    for (int mt = 0; mt < 4; mt++)
#pragma unroll
        for (int nt = 0; nt < 4; nt++)
#pragma unroll
            for (int r = 0; r < 4; r++) acc[mt][nt][r] = 0.0f;

    // BK=16 tile: thread stages row r = tid>>1, k-octet q8 = (tid&1)*8 (kpairs kp0..+3).
    auto load_tile = [&](int k0, int buf) {
        int r = tid >> 1, q8 = (tid & 1) * 8;
        int kp0 = q8 >> 1;                       // 0 or 4
        int gr = row0 + r;
        if (MODE == 0) {
            float4 va0 = make_float4(0.f, 0.f, 0.f, 0.f);
            float4 va1 = make_float4(0.f, 0.f, 0.f, 0.f);
            if (gr < M) {
                const float* ap = &Ap[(size_t)gr * K + k0 + q8];
                va0 = *(const float4*)&ap[0];
                va1 = *(const float4*)&ap[4];
            }
            float av[8] = {va0.x, va0.y, va0.z, va0.w, va1.x, va1.y, va1.z, va1.w};
            uint32_t hs[4], ls[4];
#pragma unroll
            for (int jp = 0; jp < 4; jp++) {
                float x0 = av[2 * jp], x1 = av[2 * jp + 1];
                __half h0 = __float2half_rn(x0), h1 = __float2half_rn(x1);
                hs[jp] = pack_h2(__half2float(h0), __half2float(h1));
                ls[jp] = pack_h2(x0 - __half2float(h0), x1 - __half2float(h1));
            }
            *(uint4*)&Ah[buf][r][kp0] = make_uint4(hs[0], hs[1], hs[2], hs[3]);
            *(uint4*)&Al[buf][r][kp0] = make_uint4(ls[0], ls[1], ls[2], ls[3]);
        } else {
            uint4 v = make_uint4(0u, 0u, 0u, 0u);
            if (gr < M) v = *(const uint4*)&g_agg2[(size_t)gr * K + k0 + q8];
            *(uint4*)&Ah[buf][r][kp0] = v;
        }
    };

    const int steps = K / 16;
    load_tile(0, 0);
    __syncthreads();

    const uint4* BfW = Bf + (size_t)warp_n * 4 * 32 + lane;   // + s*16*32 + nt*32
    const int rsel  = lane & 15;          // fragment row within 16-row tile
    const int khalf = (lane >> 4) * 4;    // 16B k-half selector (kpair 0 or 4)

    for (int s = 0; s < steps; s++) {
        uint4 fb[4];
#pragma unroll
        for (int nt = 0; nt < 4; nt++)
            fb[nt] = __ldg(&BfW[(size_t)s * 16 * 32 + nt * 32]);

        if (s + 1 < steps) load_tile((s + 1) * 16, (s + 1) & 1);
        const int cb = s & 1;

        uint32_t fah[4][4], fal[4][4];
#pragma unroll
        for (int mt = 0; mt < 4; mt++) {
            int m0 = warp_m * 64 + mt * 16;
            ldsm_x4(fah[mt], &Ah[cb][m0 + rsel][khalf]);
            if (MODE == 0) ldsm_x4(fal[mt], &Al[cb][m0 + rsel][khalf]);
        }
#pragma unroll
        for (int mt = 0; mt < 4; mt++)
#pragma unroll
            for (int nt = 0; nt < 4; nt++) {
                mma_f16(acc[mt][nt], fah[mt], fb[nt].x, fb[nt].y);       // Ah*Bh
                mma_f16(acc[mt][nt], fah[mt], fb[nt].z, fb[nt].w);       // Ah*Bl
                if (MODE == 0)
                    mma_f16(acc[mt][nt], fal[mt], fb[nt].x, fb[nt].y);   // Al*Bh
            }
        __syncthreads();
    }

    // Epilogue. c0,c1 -> row gid, cols 2tig,2tig+1; c2,c3 -> row gid+8.
#pragma unroll
    for (int mt = 0; mt < 4; mt++) {
#pragma unroll
        for (int nt = 0; nt < 4; nt++) {
            int col = warp_n * 32 + nt * 8 + 2 * tig;
            int ra  = row0 + warp_m * 64 + mt * 16 + gid;
            int rb  = ra + 8;
            if (MODE == 0) {
                if (ra < M) *(__half2*)&g_h1[(size_t)ra * 128 + col] =
                    __floats2half2_rn(acc[mt][nt][0], acc[mt][nt][1]);
                if (rb < M) *(__half2*)&g_h1[(size_t)rb * 128 + col] =
                    __floats2half2_rn(acc[mt][nt][2], acc[mt][nt][3]);
            } else {
                float b0 = g_bc[col], b1 = g_bc[col + 1];
                float* baseA;
                float* baseB;
                if (col < 64) {
                    baseA = outMu + (size_t)ra * D_DIM + col;
                    baseB = outMu + (size_t)rb * D_DIM + col;
                } else {
                    baseA = outSig + (size_t)ra * D_DIM + (col - 64);
                    baseB = outSig + (size_t)rb * D_DIM + (col - 64);
                }
                if (ra < M) *(float2*)baseA =
                    make_float2(acc[mt][nt][0] + b0, acc[mt][nt][1] + b1);
                if (rb < M) *(float2*)baseB =
                    make_float2(acc[mt][nt][2] + b0, acc[mt][nt][3] + b1);
            }
        }
    }
}

// ---------------- CSR gather-aggregate (fp16 h rows, fp32 accumulate) -------------
// One warp per node; each lane covers 4 features (8B fp16 load per row).
// LAYER 0: reads g_h1, writes g_h2 = relu(agg + b1) as fp16 (relu fused)
// LAYER 1: reads g_h2, writes g_agg2 as fp16 (feeds GEMM2).
template <int LAYER>
__global__ void __launch_bounds__(256)
aggregate_kernel(const float* __restrict__ b1) {
    int n    = (blockIdx.x * 256 + threadIdx.x) >> 5;
    int lane = threadIdx.x & 31;
    if (n >= N_NODES) return;

    const __half* h = (LAYER == 0) ? g_h1 : g_h2;

    float di = g_dinv[n];
    float d2 = di * di;
    float4 acc = h4_to_f4(((const uint2*)(h + (size_t)n * 128))[lane]);
    acc.x *= d2; acc.y *= d2; acc.z *= d2; acc.w *= d2;

    int r0 = g_row[n], r1 = g_row[n + 1];
    for (int base = r0; base < r1; base += 32) {
        int rem = min(r1 - base, 32);
        int2 ent = make_int2(0, 0);
        if (lane < rem) ent = g_csr[base + lane];

        int k = 0;
        for (; k + 4 <= rem; k += 4) {
            int   s0 = __shfl_sync(0xffffffffu, ent.x, k + 0);
            int   s1 = __shfl_sync(0xffffffffu, ent.x, k + 1);
            int   s2 = __shfl_sync(0xffffffffu, ent.x, k + 2);
            int   s3 = __shfl_sync(0xffffffffu, ent.x, k + 3);
            float w0 = __int_as_float(__shfl_sync(0xffffffffu, ent.y, k + 0));
            float w1 = __int_as_float(__shfl_sync(0xffffffffu, ent.y, k + 1));
            float w2 = __int_as_float(__shfl_sync(0xffffffffu, ent.y, k + 2));
            float w3 = __int_as_float(__shfl_sync(0xffffffffu, ent.y, k + 3));
            uint2 u0 = ((const uint2*)(h + (size_t)s0 * 128))[lane];
            uint2 u1 = ((const uint2*)(h + (size_t)s1 * 128))[lane];
            uint2 u2 = ((const uint2*)(h + (size_t)s2 * 128))[lane];
            uint2 u3 = ((const uint2*)(h + (size_t)s3 * 128))[lane];
            float4 v0 = h4_to_f4(u0);
            float4 v1 = h4_to_f4(u1);
            float4 v2 = h4_to_f4(u2);
            float4 v3 = h4_to_f4(u3);
            acc.x = fmaf(v0.x, w0, acc.x); acc.y = fmaf(v0.y, w0, acc.y);
            acc.z = fmaf(v0.z, w0, acc.z); acc.w = fmaf(v0.w, w0, acc.w);
            acc.x = fmaf(v1.x, w1, acc.x); acc.y = fmaf(v1.y, w1, acc.y);
            acc.z = fmaf(v1.z, w1, acc.z); acc.w = fmaf(v1.w, w1, acc.w);
            acc.x = fmaf(v2.x, w2, acc.x); acc.y = fmaf(v2.y, w2, acc.y);
            acc.z = fmaf(v2.z, w2, acc.z); acc.w = fmaf(v2.w, w2, acc.w);
            acc.x = fmaf(v3.x, w3, acc.x); acc.y = fmaf(v3.y, w3, acc.y);
            acc.z = fmaf(v3.z, w3, acc.z); acc.w = fmaf(v3.w, w3, acc.w);
        }
        for (; k < rem; k++) {
            int   s = __shfl_sync(0xffffffffu, ent.x, k);
            float w = __int_as_float(__shfl_sync(0xffffffffu, ent.y, k));
            float4 v = h4_to_f4(((const uint2*)(h + (size_t)s * 128))[lane]);
            acc.x = fmaf(v.x, w, acc.x); acc.y = fmaf(v.y, w, acc.y);
            acc.z = fmaf(v.z, w, acc.z); acc.w = fmaf(v.w, w, acc.w);
        }
    }

    if (LAYER == 0) {
        float4 b = ((const float4*)b1)[lane];
        acc.x = fmaxf(acc.x + b.x, 0.0f);
        acc.y = fmaxf(acc.y + b.y, 0.0f);
        acc.z = fmaxf(acc.z + b.z, 0.0f);
        acc.w = fmaxf(acc.w + b.w, 0.0f);
        ((uint2*)(g_h2 + (size_t)n * 128))[lane] = f4_to_h4(acc);
    } else {
        ((uint2*)(g_agg2 + (size_t)n * 128))[lane] = f4_to_h4(acc);
    }
}

// --------------------------------------------------------------------------------
extern "C" void kernel_launch(void* const* d_in, const int* in_sizes, int n_in,
                              void* d_out, int out_size) {
    const float* x    = (const float*)d_in[0];
    const int*   ei   = (const int*)d_in[1];     // edge_index: int32
    const float* W1   = (const float*)d_in[2];
    const float* b1   = (const float*)d_in[3];
    const float* Wmu  = (const float*)d_in[4];
    const float* bmu  = (const float*)d_in[5];
    const float* Wvar = (const float*)d_in[6];
    const float* bvar = (const float*)d_in[7];

    const int E = in_sizes[1] / 2;
    const int* src = ei;
    const int* dst = ei + E;

    float* outMu  = (float*)d_out;
    float* outSig = (float*)d_out + (size_t)N_NODES * D_DIM;

    const int aggBlocks = (N_NODES * 32 + 255) / 256;   // one warp per node

    // Side stream + fork/join events: created once, reused every call (the
    // captured graph is identical call-to-call; no device memory involved).
    static cudaStream_t s_csr = nullptr;
    static cudaEvent_t  s_evFork = nullptr, s_evJoin = nullptr;
    if (s_csr == nullptr) {
        cudaStreamCreateWithFlags(&s_csr, cudaStreamNonBlocking);
        cudaEventCreateWithFlags(&s_evFork, cudaEventDisableTiming);
        cudaEventCreateWithFlags(&s_evJoin, cudaEventDisableTiming);
    }

    // Fork: CSR chain + projection pack on side stream, GEMM1 on main stream.
    cudaEventRecord(s_evFork, 0);
    cudaStreamWaitEvent(s_csr, s_evFork, 0);

    pack_bfrag1_kernel<<<(16 * 16 * 32 + 255) / 256, 256>>>(W1);          // #1 main
    zero_cnt_kernel   <<<(N_NODES + 255) / 256, 256, 0, s_csr>>>();       // #2 side
    count_kernel      <<<(E + 255) / 256, 256, 0, s_csr>>>(dst, E);       // #3 side

    // #4 (ncu capture slot): layer-1 fp16 GEMM (h1) — overlaps the CSR chain
    tgemm_kernel<0><<<(N_NODES + 127) / 128, 256>>>(x, nullptr, nullptr, N_NODES, F_IN);

    scan_kernel       <<<1, 1024, 0, s_csr>>>();                          // #5 side
    fill_kernel       <<<(E + 255) / 256, 256, 0, s_csr>>>(src, dst, E);  // #6 side
    pack_bfrag2_kernel<<<(8 * 16 * 32 + 255) / 256, 256, 0, s_csr>>>(Wmu, Wvar, bmu, bvar);

    // Join: aggregates need both h1 (main) and CSR (side).
    cudaEventRecord(s_evJoin, s_csr);
    cudaStreamWaitEvent(0, s_evJoin, 0);

    // layer-1 aggregate + fused relu (writes h2, fp16)
    aggregate_kernel<0><<<aggBlocks, 256>>>(b1);

    // layer-2 aggregate (agg2, fp16)
    aggregate_kernel<1><<<aggBlocks, 256>>>(nullptr);

    // fused mu/sigma fp16 GEMM into d_out
    tgemm_kernel<1><<<(N_NODES + 127) / 128, 256>>>(nullptr, outMu, outSig, N_NODES, H_DIM);
}